// round 11
// baseline (speedup 1.0000x reference)
#include <cuda_runtime.h>
#include <cuda_fp16.h>
#include <math.h>
#include <stdint.h>

#define BATCH 4
#define NPIX  4096
#define CHIGH 256
#define CLOW  128
#define HEADS 4
#define HDIM  32
#define FFN   256

// ======================= helpers =======================
__device__ __forceinline__ uint32_t smem_u32(const void* p) {
    uint32_t a;
    asm("{ .reg .u64 t; cvta.to.shared.u64 t, %1; cvt.u32.u64 %0, t; }" : "=r"(a) : "l"(p));
    return a;
}

#define LDSM_X4(r0, r1, r2, r3, addr) \
    asm volatile("ldmatrix.sync.aligned.m8n8.x4.shared.b16 {%0,%1,%2,%3}, [%4];" \
        : "=r"(r0), "=r"(r1), "=r"(r2), "=r"(r3) : "r"(addr))
#define LDSM_X2(r0, r1, addr) \
    asm volatile("ldmatrix.sync.aligned.m8n8.x2.shared.b16 {%0,%1}, [%2];" \
        : "=r"(r0), "=r"(r1) : "r"(addr))
#define LDSM_X4_T(r0, r1, r2, r3, addr) \
    asm volatile("ldmatrix.sync.aligned.m8n8.x4.trans.shared.b16 {%0,%1,%2,%3}, [%4];" \
        : "=r"(r0), "=r"(r1), "=r"(r2), "=r"(r3) : "r"(addr))
#define LDSM_X2_T(r0, r1, addr) \
    asm volatile("ldmatrix.sync.aligned.m8n8.x2.trans.shared.b16 {%0,%1}, [%2];" \
        : "=r"(r0), "=r"(r1) : "r"(addr))
#define MMA16816(c, a, b) \
    asm volatile("mma.sync.aligned.m16n8k16.row.col.f32.f16.f16.f32 " \
        "{%0,%1,%2,%3}, {%4,%5,%6,%7}, {%8,%9}, {%0,%1,%2,%3};" \
        : "+f"((c)[0]), "+f"((c)[1]), "+f"((c)[2]), "+f"((c)[3]) \
        : "r"((a)[0]), "r"((a)[1]), "r"((a)[2]), "r"((a)[3]), "r"((b)[0]), "r"((b)[1]))
#define MMA16816H(c, a, b) \
    asm volatile("mma.sync.aligned.m16n8k16.row.col.f16.f16.f16.f16 " \
        "{%0,%1}, {%2,%3,%4,%5}, {%6,%7}, {%0,%1};" \
        : "+r"((c)[0]), "+r"((c)[1]) \
        : "r"((a)[0]), "r"((a)[1]), "r"((a)[2]), "r"((a)[3]), "r"((b)[0]), "r"((b)[1]))
#define EX2_F16X2(out, in) \
    asm("ex2.approx.f16x2 %0, %1;" : "=r"(out) : "r"(in))

__device__ __forceinline__ void cpa16(uint32_t dst, const void* src) {
    asm volatile("cp.async.ca.shared.global [%0], [%1], 16;" :: "r"(dst), "l"(src));
}
#define CP_COMMIT() asm volatile("cp.async.commit_group;" ::: "memory")
#define CP_WAIT0()  asm volatile("cp.async.wait_group 0;" ::: "memory")

__device__ __forceinline__ uint32_t pack_hf2(float a, float b) {
    __half2 h = __floats2half2_rn(a, b);
    return *(uint32_t*)&h;
}

// ======================= scratch =======================
__device__ __half g_q  [BATCH*CLOW *NPIX];   // [b][c][n], scale*log2e folded
__device__ __half g_k  [BATCH*CLOW *NPIX];
__device__ __half g_v  [BATCH*CLOW *NPIX];
__device__ __half g_ao [BATCH*CLOW *NPIX];
__device__ float  g_x  [BATCH*CLOW *NPIX];
__device__ __half g_mid[BATCH*FFN  *NPIX];
__device__ float g_part[3][BATCH][64][2];
__device__ float g_mu[3][BATCH];
__device__ float g_rs[3][BATCH];
__device__ __half g_whq[CLOW*CHIGH];
__device__ __half g_whk[CLOW*CLOW];
__device__ __half g_whv[CLOW*CLOW];
__device__ __half g_whp[CLOW*CLOW];
__device__ __half g_wh1[FFN*CLOW];
__device__ __half g_wh2[CLOW*FFN];

// ================= weight convert (fp32 -> fp16, scale folded for Wq) =================
__global__ void convert_weights(const float* __restrict__ Wq, const float* __restrict__ Wk,
                                const float* __restrict__ Wv, const float* __restrict__ Wp,
                                const float* __restrict__ W1, const float* __restrict__ W2,
                                float qscale) {
    int which = blockIdx.y;
    const float* src; __half* dst; int n; float a = 1.0f;
    switch (which) {
        case 0: src = Wq; dst = g_whq; n = CLOW*CHIGH; a = qscale; break;
        case 1: src = Wk; dst = g_whk; n = CLOW*CLOW;  break;
        case 2: src = Wv; dst = g_whv; n = CLOW*CLOW;  break;
        case 3: src = Wp; dst = g_whp; n = CLOW*CLOW;  break;
        case 4: src = W1; dst = g_wh1; n = FFN*CLOW;   break;
        default: src = W2; dst = g_wh2; n = CLOW*FFN;  break;
    }
    int i = (blockIdx.x * blockDim.x + threadIdx.x) * 4;
    if (i < n) {
        float4 v = *(const float4*)(src + i);
        uint2 p;
        p.x = pack_hf2(v.x*a, v.y*a);
        p.y = pack_hf2(v.z*a, v.w*a);
        *(uint2*)(dst + i) = p;
    }
}

// ================= GroupNorm stats (deterministic 2-stage) =================
__global__ void stats_partial2(const float* __restrict__ high, const float* __restrict__ low) {
    int b = blockIdx.x, ch = blockIdx.y, z = blockIdx.z;
    int perSample = z ? CLOW*NPIX : CHIGH*NPIX;
    int perChunk  = perSample / 32;
    const float* p = (z ? low : high) + (size_t)b*perSample + (size_t)ch*perChunk;
    float s = 0.f, ss = 0.f;
    for (int i = threadIdx.x*4; i < perChunk; i += blockDim.x*4) {
        float4 v = *(const float4*)(p + i);
        s  += v.x + v.y + v.z + v.w;
        ss += v.x*v.x + v.y*v.y + v.z*v.z + v.w*v.w;
    }
    #pragma unroll
    for (int o = 16; o; o >>= 1) {
        s  += __shfl_xor_sync(0xffffffffu, s,  o);
        ss += __shfl_xor_sync(0xffffffffu, ss, o);
    }
    __shared__ float sh[2][8];
    int w = threadIdx.x >> 5;
    if ((threadIdx.x & 31) == 0) { sh[0][w] = s; sh[1][w] = ss; }
    __syncthreads();
    if (threadIdx.x == 0) {
        float S = 0.f, SS = 0.f;
        #pragma unroll
        for (int i = 0; i < 8; i++) { S += sh[0][i]; SS += sh[1][i]; }
        g_part[z][b][ch][0] = S; g_part[z][b][ch][1] = SS;
    }
}

__global__ void stats_final(int base, float cnt0, float cnt1, int nch) {
    int b = blockIdx.x, idx = base + blockIdx.y, t = threadIdx.x;
    float cnt = blockIdx.y ? cnt1 : cnt0;
    float s = g_part[idx][b][t][0], ss = g_part[idx][b][t][1];
    if (nch > 32) { s += g_part[idx][b][t+32][0]; ss += g_part[idx][b][t+32][1]; }
    #pragma unroll
    for (int o = 16; o; o >>= 1) {
        s  += __shfl_xor_sync(0xffffffffu, s,  o);
        ss += __shfl_xor_sync(0xffffffffu, ss, o);
    }
    if (t == 0) {
        float mu = s / cnt;
        float var = ss / cnt - mu * mu;
        g_mu[idx][b] = mu;
        g_rs[idx][b] = rsqrtf(var + 1e-5f);
    }
}

// ================= dual-warpgroup TC GEMM, software-pipelined fp32 B-loads =================
// INMODE: 0 = fp32 + groupnorm affine (register-pipelined), 2 = fp16 raw (cp.async)
// EP: 1 = f16 out; 2 = fp32 out = res + gamma*acc (+stats); 3 = gelu -> f16
template<int INMODE, int EP, int GTILES, int DOSTATS>
__global__ void __launch_bounds__(256, 2)
gemm2(const float* __restrict__ INf, const __half* __restrict__ INh,
      const __half* __restrict__ WA, const __half* __restrict__ WB, int gbase1,
      int K, int cw,
      const float* __restrict__ nw, const float* __restrict__ nbias, int sidx,
      float* __restrict__ outf, __half* __restrict__ outhA, __half* __restrict__ outhB,
      const float* __restrict__ res, const float* __restrict__ gamma) {
    __shared__ __align__(16) __half sA[2][2][GTILES*64*40];
    __shared__ __align__(16) __half sB[2][32*72];

    const int tid = threadIdx.x, warp = tid >> 5, lane = tid & 31;
    const int g = warp >> 2, wi = warp & 3, wt = tid & 127;
    const int b = blockIdx.z, n0 = blockIdx.x * 64;
    const __half* Wg = g ? WB : WA;
    __half* outh = g ? outhB : outhA;
    const int gbase = g ? gbase1 : 0;

    float mu = 0.f, rs = 0.f;
    if (INMODE == 0) { mu = g_mu[sidx][b]; rs = g_rs[sidx][b]; }

    const int kB = tid >> 3, nsegB = tid & 7;   // B-stage thread map

    auto stageA = [&](int k0, int bf) {
        #pragma unroll
        for (int it = 0; it < GTILES*2; it++) {
            int idx = wt + it*128;
            int c = idx >> 2, ch = idx & 3;
            cpa16(smem_u32(&sA[bf][g][c*40 + ch*8]),
                  Wg + (size_t)(gbase + c)*K + k0 + ch*8);
        }
    };
    auto loadB = [&](int k0, float4& ra, float4& rb) {
        const float* p = &INf[((size_t)b*K + k0 + kB)*NPIX + n0 + nsegB*8];
        ra = *(const float4*)p;
        rb = *(const float4*)(p + 4);
    };
    auto storeB = [&](int k0, int bf, const float4& ra, const float4& rb) {
        int kk = k0 + kB;
        float s0 = nw[kk]*rs, t0 = nbias[kk] - mu*s0;
        uint4 o;
        o.x = pack_hf2(ra.x*s0+t0, ra.y*s0+t0);
        o.y = pack_hf2(ra.z*s0+t0, ra.w*s0+t0);
        o.z = pack_hf2(rb.x*s0+t0, rb.y*s0+t0);
        o.w = pack_hf2(rb.z*s0+t0, rb.w*s0+t0);
        *(uint4*)&sB[bf][kB*72 + nsegB*8] = o;
    };
    auto stageB_async = [&](int k0, int bf) {
        cpa16(smem_u32(&sB[bf][kB*72 + nsegB*8]),
              &INh[((size_t)b*K + k0 + kB)*NPIX + n0 + nsegB*8]);
    };

    float acc[GTILES][8][4] = {};
    const int nch = K >> 5;

    // prologue: chunk 0 fully staged
    stageA(0, 0);
    if constexpr (INMODE == 0) {
        float4 ra, rb;
        loadB(0, ra, rb);
        storeB(0, 0, ra, rb);
    } else {
        stageB_async(0, 0);
    }
    CP_COMMIT();

    for (int i = 0; i < nch; i++) {
        const int bf = i & 1;
        const bool more = (i + 1 < nch);

        float4 ra, rb;
        if (INMODE == 0 && more) loadB((i+1)*32, ra, rb);   // issue global loads EARLY (regs only)

        CP_WAIT0();
        __syncthreads();

        if (more) {
            stageA((i+1)*32, bf^1);                          // cp.async, post-sync (no WAR on sA)
            if constexpr (INMODE == 2) stageB_async((i+1)*32, bf^1);
        }

        #pragma unroll
        for (int ct = 0; ct < GTILES; ct++) {
            uint32_t qa[2][4];
            #pragma unroll
            for (int kc = 0; kc < 2; kc++) {
                uint32_t addr = smem_u32(&sA[bf][g][(ct*64 + wi*16 + (lane & 15))*40
                                                    + kc*16 + (lane >> 4)*8]);
                LDSM_X4(qa[kc][0], qa[kc][1], qa[kc][2], qa[kc][3], addr);
            }
            #pragma unroll
            for (int nt = 0; nt < 8; nt++) {
                uint32_t b0[2], b1[2];
                uint32_t a0 = smem_u32(&sB[bf][(lane & 15)*72 + nt*8]);
                LDSM_X2_T(b0[0], b0[1], a0);
                LDSM_X2_T(b1[0], b1[1], a0 + 16*72*2);
                MMA16816(acc[ct][nt], qa[0], b0);
                MMA16816(acc[ct][nt], qa[1], b1);
            }
        }

        if (more) {
            if constexpr (INMODE == 0) storeB((i+1)*32, bf^1, ra, rb);  // consume loads AFTER MMAs
            CP_COMMIT();
        }
    }

    float s_s = 0.f, s_ss = 0.f;
    #pragma unroll
    for (int ct = 0; ct < GTILES; ct++) {
        #pragma unroll
        for (int nt = 0; nt < 8; nt++) {
            int n = nt*8 + (lane & 3)*2;
            int cA = gbase + ct*64 + wi*16 + (lane >> 2), cB = cA + 8;
            size_t oA = ((size_t)b*cw + cA)*NPIX + n0 + n;
            size_t oB = ((size_t)b*cw + cB)*NPIX + n0 + n;
            if constexpr (EP == 1) {
                *(uint32_t*)&outh[oA] = pack_hf2(acc[ct][nt][0], acc[ct][nt][1]);
                *(uint32_t*)&outh[oB] = pack_hf2(acc[ct][nt][2], acc[ct][nt][3]);
            } else if constexpr (EP == 2) {
                float gm = gamma[0];
                float2 rA = *(const float2*)&res[oA];
                float2 rB = *(const float2*)&res[oB];
                float v0 = rA.x + gm*acc[ct][nt][0], v1 = rA.y + gm*acc[ct][nt][1];
                float v2 = rB.x + gm*acc[ct][nt][2], v3 = rB.y + gm*acc[ct][nt][3];
                *(float2*)&outf[oA] = make_float2(v0, v1);
                *(float2*)&outf[oB] = make_float2(v2, v3);
                if (DOSTATS) {
                    s_s  += (v0 + v1) + (v2 + v3);
                    s_ss += v0*v0 + v1*v1 + v2*v2 + v3*v3;
                }
            } else {
                float v0 = acc[ct][nt][0], v1 = acc[ct][nt][1];
                float v2 = acc[ct][nt][2], v3 = acc[ct][nt][3];
                v0 = 0.5f*v0*(1.0f + erff(v0*0.70710678118654752f));
                v1 = 0.5f*v1*(1.0f + erff(v1*0.70710678118654752f));
                v2 = 0.5f*v2*(1.0f + erff(v2*0.70710678118654752f));
                v3 = 0.5f*v3*(1.0f + erff(v3*0.70710678118654752f));
                *(uint32_t*)&outh[oA] = pack_hf2(v0, v1);
                *(uint32_t*)&outh[oB] = pack_hf2(v2, v3);
            }
        }
    }
    if constexpr (DOSTATS) {
        #pragma unroll
        for (int o = 16; o; o >>= 1) {
            s_s  += __shfl_xor_sync(0xffffffffu, s_s,  o);
            s_ss += __shfl_xor_sync(0xffffffffu, s_ss, o);
        }
        __shared__ float shr[2][8];
        if (lane == 0) { shr[0][warp] = s_s; shr[1][warp] = s_ss; }
        __syncthreads();
        if (tid == 0) {
            float S = 0.f, SS = 0.f;
            #pragma unroll
            for (int i = 0; i < 8; i++) { S += shr[0][i]; SS += shr[1][i]; }
            g_part[2][b][blockIdx.x][0] = S; g_part[2][b][blockIdx.x][1] = SS;
        }
    }
}

// ================= flash attention (ALL-fp16 mma accum, exp2-domain, V-ones l-sum) =================
#define QSTR 136
#define KVSTR 72

__device__ __forceinline__ void prefetch_kv(__half* sk, __half* sv,
        const __half* Kb, const __half* Vb, int n0, int tid) {
    #pragma unroll
    for (int i = 0; i < 2; i++) {
        int ch = tid + i * 128;
        int row = ch >> 3, col = ch & 7;
        cpa16(smem_u32(&sk[row*KVSTR + col*8]), Kb + (size_t)row*NPIX + n0 + col*8);
    }
    #pragma unroll
    for (int i = 0; i < 2; i++) {
        int ch = tid + i * 128;
        int row = ch >> 3, col = ch & 7;
        cpa16(smem_u32(&sv[row*KVSTR + col*8]), Vb + (size_t)row*NPIX + n0 + col*8);
    }
}

__global__ void __launch_bounds__(128, 3)
flash_mma(const __half* __restrict__ Qg, const __half* __restrict__ Kg,
          const __half* __restrict__ Vg, __half* __restrict__ Og) {
    __shared__ __align__(16) __half sQ[32*QSTR];
    __shared__ __align__(16) __half sK[2][32*KVSTR];
    __shared__ __align__(16) __half sV[2][40*KVSTR];
    __shared__ __align__(16) float sT[32*132];

    const int tid = threadIdx.x, warp = tid >> 5, lane = tid & 31;
    const int bh = blockIdx.y, m0 = blockIdx.x * 128;
    const __half* Qb = Qg + (size_t)bh * HDIM * NPIX + m0;
    const __half* Kb = Kg + (size_t)bh * HDIM * NPIX;
    const __half* Vb = Vg + (size_t)bh * HDIM * NPIX;

    {
        int bfi = tid >> 6, row = 32 + ((tid >> 3) & 7), chk = tid & 7;
        float v = (row == 32) ? 1.0f : 0.0f;
        uint32_t hv = pack_hf2(v, v);
        uint4 q4 = make_uint4(hv, hv, hv, hv);
        *(uint4*)&sV[bfi][row*KVSTR + chk*8] = q4;
    }

    #pragma unroll
    for (int i = 0; i < 4; i++) {
        int ch = tid + i * 128;
        int row = ch >> 4, col = ch & 15;
        *(uint4*)&sQ[row*QSTR + col*8] = *(const uint4*)(Qb + (size_t)row*NPIX + col*8);
    }
    prefetch_kv(sK[0], sV[0], Kb, Vb, 0, tid);
    CP_COMMIT();
    __syncthreads();

    uint32_t qa[2][2][4];
    #pragma unroll
    for (int mb = 0; mb < 2; mb++)
        #pragma unroll
        for (int kc = 0; kc < 2; kc++) {
            uint32_t addr = smem_u32(&sQ[(kc*16 + ((lane >> 4) & 1)*8 + (lane & 7))*QSTR
                                         + warp*32 + mb*16 + ((lane >> 3) & 1)*8]);
            LDSM_X4_T(qa[mb][kc][0], qa[mb][kc][1], qa[mb][kc][2], qa[mb][kc][3], addr);
        }

    uint32_t Oc[2][5][2] = {};

    for (int nb = 0; nb < 64; nb++) {
        const int buf = nb & 1;
        CP_WAIT0();
        __syncthreads();
        if (nb < 63) {
            prefetch_kv(sK[buf^1], sV[buf^1], Kb, Vb, (nb+1)*64, tid);
            CP_COMMIT();
        }

        uint32_t pa[2][4][4];
        #pragma unroll
        for (int nt = 0; nt < 8; nt++) {
            uint32_t bk0[2], bk1[2];
            uint32_t a0 = smem_u32(&sK[buf][(lane & 15)*KVSTR + nt*8]);
            LDSM_X2_T(bk0[0], bk0[1], a0);
            LDSM_X2_T(bk1[0], bk1[1], a0 + 16*KVSTR*2);
            #pragma unroll
            for (int mb = 0; mb < 2; mb++) {
                uint32_t S[2] = {0u, 0u};
                MMA16816H(S, qa[mb][0], bk0);
                MMA16816H(S, qa[mb][1], bk1);
                EX2_F16X2(S[0], S[0]);
                EX2_F16X2(S[1], S[1]);
                pa[mb][nt >> 1][(nt & 1)*2 + 0] = S[0];
                pa[mb][nt >> 1][(nt & 1)*2 + 1] = S[1];
            }
        }

        #pragma unroll
        for (int kc = 0; kc < 4; kc++)
            #pragma unroll
            for (int dt = 0; dt < 5; dt++) {
                uint32_t vb[2];
                uint32_t addr = smem_u32(&sV[buf][(dt*8 + (lane & 7))*KVSTR
                                                  + kc*16 + ((lane >> 3) & 1)*8]);
                LDSM_X2(vb[0], vb[1], addr);
                MMA16816H(Oc[0][dt], pa[0][kc], vb);
                MMA16816H(Oc[1][dt], pa[1][kc], vb);
            }
    }

    float inv[2][2];
    #pragma unroll
    for (int mb = 0; mb < 2; mb++) {
        __half2 h0 = *(__half2*)&Oc[mb][4][0];
        __half2 h1 = *(__half2*)&Oc[mb][4][1];
        float l0 = __shfl_sync(0xffffffffu, __half2float(h0.x), lane & 28);
        float l1 = __shfl_sync(0xffffffffu, __half2float(h1.x), lane & 28);
        inv[mb][0] = 1.0f / l0;
        inv[mb][1] = 1.0f / l1;
    }

    #pragma unroll
    for (int mb = 0; mb < 2; mb++) {
        int r = warp*32 + mb*16 + (lane >> 2);
        #pragma unroll
        for (int dt = 0; dt < 4; dt++) {
            int d = dt*8 + (lane & 3)*2;
            __half2 p0 = *(__half2*)&Oc[mb][dt][0];
            __half2 p1 = *(__half2*)&Oc[mb][dt][1];
            sT[(d+0)*132 + r    ] = __half2float(p0.x)*inv[mb][0];
            sT[(d+1)*132 + r    ] = __half2float(p0.y)*inv[mb][0];
            sT[(d+0)*132 + r + 8] = __half2float(p1.x)*inv[mb][1];
            sT[(d+1)*132 + r + 8] = __half2float(p1.y)*inv[mb][1];
        }
    }
    __syncthreads();
    __half* aob = Og + (size_t)bh * HDIM * NPIX + m0;
    #pragma unroll
    for (int i = 0; i < 8; i++) {
        int idx = tid + i*128;
        int d = idx >> 5, seg = idx & 31;
        const float* src = &sT[d*132 + seg*4];
        uint2 p;
        p.x = pack_hf2(src[0], src[1]);
        p.y = pack_hf2(src[2], src[3]);
        *(uint2*)(aob + (size_t)d*NPIX + seg*4) = p;
    }
}

// ================= launch =================
extern "C" void kernel_launch(void* const* d_in, const int* in_sizes, int n_in,
                              void* d_out, int out_size) {
    const float* high  = (const float*)d_in[0];
    const float* low   = (const float*)d_in[1];
    const float* nhw   = (const float*)d_in[2];
    const float* nhb   = (const float*)d_in[3];
    const float* nlw   = (const float*)d_in[4];
    const float* nlb   = (const float*)d_in[5];
    const float* nfw   = (const float*)d_in[6];
    const float* nfb   = (const float*)d_in[7];
    const float* Wq    = (const float*)d_in[8];
    const float* Wk    = (const float*)d_in[9];
    const float* Wv    = (const float*)d_in[10];
    const float* Wproj = (const float*)d_in[11];
    const float* Wffn1 = (const float*)d_in[12];
    const float* Wffn2 = (const float*)d_in[13];
    const float* ga    = (const float*)d_in[14];
    const float* gf    = (const float*)d_in[15];
    float* out = (float*)d_out;

    float *x;
    __half *q, *k, *v, *ao, *mid, *whq, *whk, *whv, *whp, *wh1, *wh2;
    cudaGetSymbolAddress((void**)&q,   g_q);
    cudaGetSymbolAddress((void**)&k,   g_k);
    cudaGetSymbolAddress((void**)&v,   g_v);
    cudaGetSymbolAddress((void**)&ao,  g_ao);
    cudaGetSymbolAddress((void**)&x,   g_x);
    cudaGetSymbolAddress((void**)&mid, g_mid);
    cudaGetSymbolAddress((void**)&whq, g_whq);
    cudaGetSymbolAddress((void**)&whk, g_whk);
    cudaGetSymbolAddress((void**)&whv, g_whv);
    cudaGetSymbolAddress((void**)&whp, g_whp);
    cudaGetSymbolAddress((void**)&wh1, g_wh1);
    cudaGetSymbolAddress((void**)&wh2, g_wh2);

    const float scale = 0.17677669529663687f * 1.44269504088896340736f; // 1/sqrt(32)*log2e
    dim3 gg(NPIX/64, 1, BATCH);

    convert_weights<<<dim3(32, 6), 256>>>(Wq, Wk, Wv, Wproj, Wffn1, Wffn2, scale);
    stats_partial2<<<dim3(BATCH, 32, 2), 256>>>(high, low);
    stats_final<<<dim3(BATCH, 2), 32>>>(0, (float)(CHIGH*NPIX), (float)(CLOW*NPIX), 32);

    gemm2<0,1,1,0><<<gg, 256>>>(high, nullptr, whq, whq, 64, CHIGH, CLOW,
                                nhw, nhb, 0, nullptr, q, q, nullptr, nullptr);
    gemm2<0,1,2,0><<<gg, 256>>>(low, nullptr, whk, whv, 0, CLOW, CLOW,
                                nlw, nlb, 1, nullptr, k, v, nullptr, nullptr);

    flash_mma<<<dim3(NPIX/128, BATCH*HEADS), 128>>>(q, k, v, ao);

    gemm2<2,2,1,1><<<gg, 256>>>(nullptr, ao, whp, whp, 64, CLOW, CLOW,
                                nullptr, nullptr, 0, x, nullptr, nullptr, low, ga);
    stats_final<<<dim3(BATCH, 1), 32>>>(2, (float)(CLOW*NPIX), (float)(CLOW*NPIX), 64);

    gemm2<0,3,2,0><<<gg, 256>>>(x, nullptr, wh1, wh1, 128, CLOW, FFN,
                                nfw, nfb, 2, nullptr, mid, mid, nullptr, nullptr);
    gemm2<2,2,1,0><<<gg, 256>>>(nullptr, mid, wh2, wh2, 64, FFN, CLOW,
                                nullptr, nullptr, 0, out, nullptr, nullptr, x, gf);

    (void)in_sizes; (void)n_in; (void)out_size;
}

// round 12
// speedup vs baseline: 1.0148x; 1.0148x over previous
#include <cuda_runtime.h>
#include <cuda_fp16.h>
#include <math.h>
#include <stdint.h>

#define BATCH 4
#define NPIX  4096
#define CHIGH 256
#define CLOW  128
#define HEADS 4
#define HDIM  32
#define FFN   256

// ======================= helpers =======================
__device__ __forceinline__ uint32_t smem_u32(const void* p) {
    uint32_t a;
    asm("{ .reg .u64 t; cvta.to.shared.u64 t, %1; cvt.u32.u64 %0, t; }" : "=r"(a) : "l"(p));
    return a;
}

#define LDSM_X4(r0, r1, r2, r3, addr) \
    asm volatile("ldmatrix.sync.aligned.m8n8.x4.shared.b16 {%0,%1,%2,%3}, [%4];" \
        : "=r"(r0), "=r"(r1), "=r"(r2), "=r"(r3) : "r"(addr))
#define LDSM_X2(r0, r1, addr) \
    asm volatile("ldmatrix.sync.aligned.m8n8.x2.shared.b16 {%0,%1}, [%2];" \
        : "=r"(r0), "=r"(r1) : "r"(addr))
#define LDSM_X4_T(r0, r1, r2, r3, addr) \
    asm volatile("ldmatrix.sync.aligned.m8n8.x4.trans.shared.b16 {%0,%1,%2,%3}, [%4];" \
        : "=r"(r0), "=r"(r1), "=r"(r2), "=r"(r3) : "r"(addr))
#define LDSM_X2_T(r0, r1, addr) \
    asm volatile("ldmatrix.sync.aligned.m8n8.x2.trans.shared.b16 {%0,%1}, [%2];" \
        : "=r"(r0), "=r"(r1) : "r"(addr))
#define MMA16816(c, a, b) \
    asm volatile("mma.sync.aligned.m16n8k16.row.col.f32.f16.f16.f32 " \
        "{%0,%1,%2,%3}, {%4,%5,%6,%7}, {%8,%9}, {%0,%1,%2,%3};" \
        : "+f"((c)[0]), "+f"((c)[1]), "+f"((c)[2]), "+f"((c)[3]) \
        : "r"((a)[0]), "r"((a)[1]), "r"((a)[2]), "r"((a)[3]), "r"((b)[0]), "r"((b)[1]))
#define MMA16816H(c, a, b) \
    asm volatile("mma.sync.aligned.m16n8k16.row.col.f16.f16.f16.f16 " \
        "{%0,%1}, {%2,%3,%4,%5}, {%6,%7}, {%0,%1};" \
        : "+r"((c)[0]), "+r"((c)[1]) \
        : "r"((a)[0]), "r"((a)[1]), "r"((a)[2]), "r"((a)[3]), "r"((b)[0]), "r"((b)[1]))
#define EX2_F16X2(out, in) \
    asm("ex2.approx.f16x2 %0, %1;" : "=r"(out) : "r"(in))

__device__ __forceinline__ void cpa16(uint32_t dst, const void* src) {
    asm volatile("cp.async.ca.shared.global [%0], [%1], 16;" :: "r"(dst), "l"(src));
}
#define CP_COMMIT() asm volatile("cp.async.commit_group;" ::: "memory")
#define CP_WAIT0()  asm volatile("cp.async.wait_group 0;" ::: "memory")

__device__ __forceinline__ uint32_t pack_hf2(float a, float b) {
    __half2 h = __floats2half2_rn(a, b);
    return *(uint32_t*)&h;
}

// ======================= scratch =======================
__device__ __half g_q  [BATCH*CLOW *NPIX];   // [b][c][n], scale*log2e folded
__device__ __half g_k  [BATCH*CLOW *NPIX];
__device__ __half g_v  [BATCH*CLOW *NPIX];
__device__ __half g_ao [BATCH*CLOW *NPIX];
__device__ float  g_x  [BATCH*CLOW *NPIX];
__device__ __half g_mid[BATCH*FFN  *NPIX];
__device__ float g_part[3][BATCH][64][2];
__device__ __half g_whq[CLOW*CHIGH];
__device__ __half g_whk[CLOW*CLOW];
__device__ __half g_whv[CLOW*CLOW];
__device__ __half g_whp[CLOW*CLOW];
__device__ __half g_wh1[FFN*CLOW];
__device__ __half g_wh2[CLOW*FFN];

// ================= weight convert (fp32 -> fp16, scale folded for Wq) =================
__global__ void convert_weights(const float* __restrict__ Wq, const float* __restrict__ Wk,
                                const float* __restrict__ Wv, const float* __restrict__ Wp,
                                const float* __restrict__ W1, const float* __restrict__ W2,
                                float qscale) {
    int which = blockIdx.y;
    const float* src; __half* dst; int n; float a = 1.0f;
    switch (which) {
        case 0: src = Wq; dst = g_whq; n = CLOW*CHIGH; a = qscale; break;
        case 1: src = Wk; dst = g_whk; n = CLOW*CLOW;  break;
        case 2: src = Wv; dst = g_whv; n = CLOW*CLOW;  break;
        case 3: src = Wp; dst = g_whp; n = CLOW*CLOW;  break;
        case 4: src = W1; dst = g_wh1; n = FFN*CLOW;   break;
        default: src = W2; dst = g_wh2; n = CLOW*FFN;  break;
    }
    int i = (blockIdx.x * blockDim.x + threadIdx.x) * 4;
    if (i < n) {
        float4 v = *(const float4*)(src + i);
        uint2 p;
        p.x = pack_hf2(v.x*a, v.y*a);
        p.y = pack_hf2(v.z*a, v.w*a);
        *(uint2*)(dst + i) = p;
    }
}

// ================= GroupNorm stats partials (deterministic) =================
__global__ void stats_partial2(const float* __restrict__ high, const float* __restrict__ low) {
    int b = blockIdx.x, ch = blockIdx.y, z = blockIdx.z;
    int perSample = z ? CLOW*NPIX : CHIGH*NPIX;
    int perChunk  = perSample / 32;
    const float* p = (z ? low : high) + (size_t)b*perSample + (size_t)ch*perChunk;
    float s = 0.f, ss = 0.f;
    for (int i = threadIdx.x*4; i < perChunk; i += blockDim.x*4) {
        float4 v = *(const float4*)(p + i);
        s  += v.x + v.y + v.z + v.w;
        ss += v.x*v.x + v.y*v.y + v.z*v.z + v.w*v.w;
    }
    #pragma unroll
    for (int o = 16; o; o >>= 1) {
        s  += __shfl_xor_sync(0xffffffffu, s,  o);
        ss += __shfl_xor_sync(0xffffffffu, ss, o);
    }
    __shared__ float sh[2][8];
    int w = threadIdx.x >> 5;
    if ((threadIdx.x & 31) == 0) { sh[0][w] = s; sh[1][w] = ss; }
    __syncthreads();
    if (threadIdx.x == 0) {
        float S = 0.f, SS = 0.f;
        #pragma unroll
        for (int i = 0; i < 8; i++) { S += sh[0][i]; SS += sh[1][i]; }
        g_part[z][b][ch][0] = S; g_part[z][b][ch][1] = SS;
    }
}

// ================= dual-warpgroup TC GEMM, inlined stats + pipelined fp32 B =================
// INMODE: 0 = fp32 + groupnorm affine (stats reduced in-kernel), 2 = fp16 raw (cp.async)
// EP: 1 = f16 out; 2 = fp32 out = res + gamma*acc (+stats partials); 3 = gelu -> f16
template<int INMODE, int EP, int GTILES, int DOSTATS>
__global__ void __launch_bounds__(256, 2)
gemm2(const float* __restrict__ INf, const __half* __restrict__ INh,
      const __half* __restrict__ WA, const __half* __restrict__ WB, int gbase1,
      int K, int cw,
      const float* __restrict__ nw, const float* __restrict__ nbias, int sidx, int nchp,
      float* __restrict__ outf, __half* __restrict__ outhA, __half* __restrict__ outhB,
      const float* __restrict__ res, const float* __restrict__ gamma) {
    __shared__ __align__(16) __half sA[2][2][GTILES*64*40];
    __shared__ __align__(16) __half sB[2][32*72];
    __shared__ float s_stat[2];

    const int tid = threadIdx.x, warp = tid >> 5, lane = tid & 31;
    const int g = warp >> 2, wi = warp & 3, wt = tid & 127;
    const int b = blockIdx.z, n0 = blockIdx.x * 64;
    const __half* Wg = g ? WB : WA;
    __half* outh = g ? outhB : outhA;
    const int gbase = g ? gbase1 : 0;

    float mu = 0.f, rs = 0.f;
    if constexpr (INMODE == 0) {
        // in-kernel stats finalization (replaces stats_final launch)
        if (tid < 32) {
            float s = g_part[sidx][b][tid][0], ss = g_part[sidx][b][tid][1];
            if (nchp > 32) { s += g_part[sidx][b][tid+32][0]; ss += g_part[sidx][b][tid+32][1]; }
            #pragma unroll
            for (int o = 16; o; o >>= 1) {
                s  += __shfl_xor_sync(0xffffffffu, s,  o);
                ss += __shfl_xor_sync(0xffffffffu, ss, o);
            }
            if (tid == 0) {
                float cnt = (float)K * (float)NPIX;
                float m = s / cnt;
                float var = ss / cnt - m * m;
                s_stat[0] = m;
                s_stat[1] = rsqrtf(var + 1e-5f);
            }
        }
        __syncthreads();
        mu = s_stat[0]; rs = s_stat[1];
    }

    const int kB = tid >> 3, nsegB = tid & 7;   // B-stage thread map

    auto stageA = [&](int k0, int bf) {
        #pragma unroll
        for (int it = 0; it < GTILES*2; it++) {
            int idx = wt + it*128;
            int c = idx >> 2, ch = idx & 3;
            cpa16(smem_u32(&sA[bf][g][c*40 + ch*8]),
                  Wg + (size_t)(gbase + c)*K + k0 + ch*8);
        }
    };
    auto loadB = [&](int k0, float4& ra, float4& rb) {
        const float* p = &INf[((size_t)b*K + k0 + kB)*NPIX + n0 + nsegB*8];
        ra = *(const float4*)p;
        rb = *(const float4*)(p + 4);
    };
    auto storeB = [&](int k0, int bf, const float4& ra, const float4& rb) {
        int kk = k0 + kB;
        float s0 = nw[kk]*rs, t0 = nbias[kk] - mu*s0;
        uint4 o;
        o.x = pack_hf2(ra.x*s0+t0, ra.y*s0+t0);
        o.y = pack_hf2(ra.z*s0+t0, ra.w*s0+t0);
        o.z = pack_hf2(rb.x*s0+t0, rb.y*s0+t0);
        o.w = pack_hf2(rb.z*s0+t0, rb.w*s0+t0);
        *(uint4*)&sB[bf][kB*72 + nsegB*8] = o;
    };
    auto stageB_async = [&](int k0, int bf) {
        cpa16(smem_u32(&sB[bf][kB*72 + nsegB*8]),
              &INh[((size_t)b*K + k0 + kB)*NPIX + n0 + nsegB*8]);
    };

    float acc[GTILES][8][4] = {};
    const int nch = K >> 5;

    stageA(0, 0);
    if constexpr (INMODE == 0) {
        float4 ra, rb;
        loadB(0, ra, rb);
        storeB(0, 0, ra, rb);
    } else {
        stageB_async(0, 0);
    }
    CP_COMMIT();

    for (int i = 0; i < nch; i++) {
        const int bf = i & 1;
        const bool more = (i + 1 < nch);

        float4 ra, rb;
        if (INMODE == 0 && more) loadB((i+1)*32, ra, rb);   // early global loads (regs only)

        CP_WAIT0();
        __syncthreads();

        if (more) {
            stageA((i+1)*32, bf^1);
            if constexpr (INMODE == 2) stageB_async((i+1)*32, bf^1);
        }

        #pragma unroll
        for (int ct = 0; ct < GTILES; ct++) {
            uint32_t qa[2][4];
            #pragma unroll
            for (int kc = 0; kc < 2; kc++) {
                uint32_t addr = smem_u32(&sA[bf][g][(ct*64 + wi*16 + (lane & 15))*40
                                                    + kc*16 + (lane >> 4)*8]);
                LDSM_X4(qa[kc][0], qa[kc][1], qa[kc][2], qa[kc][3], addr);
            }
            #pragma unroll
            for (int nt = 0; nt < 8; nt++) {
                uint32_t b0[2], b1[2];
                uint32_t a0 = smem_u32(&sB[bf][(lane & 15)*72 + nt*8]);
                LDSM_X2_T(b0[0], b0[1], a0);
                LDSM_X2_T(b1[0], b1[1], a0 + 16*72*2);
                MMA16816(acc[ct][nt], qa[0], b0);
                MMA16816(acc[ct][nt], qa[1], b1);
            }
        }

        if (more) {
            if constexpr (INMODE == 0) storeB((i+1)*32, bf^1, ra, rb);
            CP_COMMIT();
        }
    }

    float s_s = 0.f, s_ss = 0.f;
    #pragma unroll
    for (int ct = 0; ct < GTILES; ct++) {
        #pragma unroll
        for (int nt = 0; nt < 8; nt++) {
            int n = nt*8 + (lane & 3)*2;
            int cA = gbase + ct*64 + wi*16 + (lane >> 2), cB = cA + 8;
            size_t oA = ((size_t)b*cw + cA)*NPIX + n0 + n;
            size_t oB = ((size_t)b*cw + cB)*NPIX + n0 + n;
            if constexpr (EP == 1) {
                *(uint32_t*)&outh[oA] = pack_hf2(acc[ct][nt][0], acc[ct][nt][1]);
                *(uint32_t*)&outh[oB] = pack_hf2(acc[ct][nt][2], acc[ct][nt][3]);
            } else if constexpr (EP == 2) {
                float gm = gamma[0];
                float2 rA = *(const float2*)&res[oA];
                float2 rB = *(const float2*)&res[oB];
                float v0 = rA.x + gm*acc[ct][nt][0], v1 = rA.y + gm*acc[ct][nt][1];
                float v2 = rB.x + gm*acc[ct][nt][2], v3 = rB.y + gm*acc[ct][nt][3];
                *(float2*)&outf[oA] = make_float2(v0, v1);
                *(float2*)&outf[oB] = make_float2(v2, v3);
                if (DOSTATS) {
                    s_s  += (v0 + v1) + (v2 + v3);
                    s_ss += v0*v0 + v1*v1 + v2*v2 + v3*v3;
                }
            } else {
                float v0 = acc[ct][nt][0], v1 = acc[ct][nt][1];
                float v2 = acc[ct][nt][2], v3 = acc[ct][nt][3];
                v0 = 0.5f*v0*(1.0f + erff(v0*0.70710678118654752f));
                v1 = 0.5f*v1*(1.0f + erff(v1*0.70710678118654752f));
                v2 = 0.5f*v2*(1.0f + erff(v2*0.70710678118654752f));
                v3 = 0.5f*v3*(1.0f + erff(v3*0.70710678118654752f));
                *(uint32_t*)&outh[oA] = pack_hf2(v0, v1);
                *(uint32_t*)&outh[oB] = pack_hf2(v2, v3);
            }
        }
    }
    if constexpr (DOSTATS) {
        #pragma unroll
        for (int o = 16; o; o >>= 1) {
            s_s  += __shfl_xor_sync(0xffffffffu, s_s,  o);
            s_ss += __shfl_xor_sync(0xffffffffu, s_ss, o);
        }
        __shared__ float shr[2][8];
        if (lane == 0) { shr[0][warp] = s_s; shr[1][warp] = s_ss; }
        __syncthreads();
        if (tid == 0) {
            float S = 0.f, SS = 0.f;
            #pragma unroll
            for (int i = 0; i < 8; i++) { S += shr[0][i]; SS += shr[1][i]; }
            g_part[2][b][blockIdx.x][0] = S; g_part[2][b][blockIdx.x][1] = SS;
        }
    }
}

// ================= flash attention (ALL-fp16 mma accum, exp2-domain, V-ones l-sum) =================
#define QSTR 136
#define KVSTR 72

__device__ __forceinline__ void prefetch_kv(__half* sk, __half* sv,
        const __half* Kb, const __half* Vb, int n0, int tid) {
    #pragma unroll
    for (int i = 0; i < 2; i++) {
        int ch = tid + i * 128;
        int row = ch >> 3, col = ch & 7;
        cpa16(smem_u32(&sk[row*KVSTR + col*8]), Kb + (size_t)row*NPIX + n0 + col*8);
    }
    #pragma unroll
    for (int i = 0; i < 2; i++) {
        int ch = tid + i * 128;
        int row = ch >> 3, col = ch & 7;
        cpa16(smem_u32(&sv[row*KVSTR + col*8]), Vb + (size_t)row*NPIX + n0 + col*8);
    }
}

__global__ void __launch_bounds__(128, 3)
flash_mma(const __half* __restrict__ Qg, const __half* __restrict__ Kg,
          const __half* __restrict__ Vg, __half* __restrict__ Og) {
    __shared__ __align__(16) __half sQ[32*QSTR];
    __shared__ __align__(16) __half sK[2][32*KVSTR];
    __shared__ __align__(16) __half sV[2][40*KVSTR];
    __shared__ __align__(16) float sT[32*132];

    const int tid = threadIdx.x, warp = tid >> 5, lane = tid & 31;
    const int bh = blockIdx.y, m0 = blockIdx.x * 128;
    const __half* Qb = Qg + (size_t)bh * HDIM * NPIX + m0;
    const __half* Kb = Kg + (size_t)bh * HDIM * NPIX;
    const __half* Vb = Vg + (size_t)bh * HDIM * NPIX;

    {
        int bfi = tid >> 6, row = 32 + ((tid >> 3) & 7), chk = tid & 7;
        float v = (row == 32) ? 1.0f : 0.0f;
        uint32_t hv = pack_hf2(v, v);
        uint4 q4 = make_uint4(hv, hv, hv, hv);
        *(uint4*)&sV[bfi][row*KVSTR + chk*8] = q4;
    }

    #pragma unroll
    for (int i = 0; i < 4; i++) {
        int ch = tid + i * 128;
        int row = ch >> 4, col = ch & 15;
        *(uint4*)&sQ[row*QSTR + col*8] = *(const uint4*)(Qb + (size_t)row*NPIX + col*8);
    }
    prefetch_kv(sK[0], sV[0], Kb, Vb, 0, tid);
    CP_COMMIT();
    __syncthreads();

    uint32_t qa[2][2][4];
    #pragma unroll
    for (int mb = 0; mb < 2; mb++)
        #pragma unroll
        for (int kc = 0; kc < 2; kc++) {
            uint32_t addr = smem_u32(&sQ[(kc*16 + ((lane >> 4) & 1)*8 + (lane & 7))*QSTR
                                         + warp*32 + mb*16 + ((lane >> 3) & 1)*8]);
            LDSM_X4_T(qa[mb][kc][0], qa[mb][kc][1], qa[mb][kc][2], qa[mb][kc][3], addr);
        }

    uint32_t Oc[2][5][2] = {};

    for (int nb = 0; nb < 64; nb++) {
        const int buf = nb & 1;
        CP_WAIT0();
        __syncthreads();
        if (nb < 63) {
            prefetch_kv(sK[buf^1], sV[buf^1], Kb, Vb, (nb+1)*64, tid);
            CP_COMMIT();
        }

        uint32_t pa[2][4][4];
        #pragma unroll
        for (int nt = 0; nt < 8; nt++) {
            uint32_t bk0[2], bk1[2];
            uint32_t a0 = smem_u32(&sK[buf][(lane & 15)*KVSTR + nt*8]);
            LDSM_X2_T(bk0[0], bk0[1], a0);
            LDSM_X2_T(bk1[0], bk1[1], a0 + 16*KVSTR*2);
            #pragma unroll
            for (int mb = 0; mb < 2; mb++) {
                uint32_t S[2] = {0u, 0u};
                MMA16816H(S, qa[mb][0], bk0);
                MMA16816H(S, qa[mb][1], bk1);
                EX2_F16X2(S[0], S[0]);
                EX2_F16X2(S[1], S[1]);
                pa[mb][nt >> 1][(nt & 1)*2 + 0] = S[0];
                pa[mb][nt >> 1][(nt & 1)*2 + 1] = S[1];
            }
        }

        #pragma unroll
        for (int kc = 0; kc < 4; kc++)
            #pragma unroll
            for (int dt = 0; dt < 5; dt++) {
                uint32_t vb[2];
                uint32_t addr = smem_u32(&sV[buf][(dt*8 + (lane & 7))*KVSTR
                                                  + kc*16 + ((lane >> 3) & 1)*8]);
                LDSM_X2(vb[0], vb[1], addr);
                MMA16816H(Oc[0][dt], pa[0][kc], vb);
                MMA16816H(Oc[1][dt], pa[1][kc], vb);
            }
    }

    float inv[2][2];
    #pragma unroll
    for (int mb = 0; mb < 2; mb++) {
        __half2 h0 = *(__half2*)&Oc[mb][4][0];
        __half2 h1 = *(__half2*)&Oc[mb][4][1];
        float l0 = __shfl_sync(0xffffffffu, __half2float(h0.x), lane & 28);
        float l1 = __shfl_sync(0xffffffffu, __half2float(h1.x), lane & 28);
        inv[mb][0] = 1.0f / l0;
        inv[mb][1] = 1.0f / l1;
    }

    #pragma unroll
    for (int mb = 0; mb < 2; mb++) {
        int r = warp*32 + mb*16 + (lane >> 2);
        #pragma unroll
        for (int dt = 0; dt < 4; dt++) {
            int d = dt*8 + (lane & 3)*2;
            __half2 p0 = *(__half2*)&Oc[mb][dt][0];
            __half2 p1 = *(__half2*)&Oc[mb][dt][1];
            sT[(d+0)*132 + r    ] = __half2float(p0.x)*inv[mb][0];
            sT[(d+1)*132 + r    ] = __half2float(p0.y)*inv[mb][0];
            sT[(d+0)*132 + r + 8] = __half2float(p1.x)*inv[mb][1];
            sT[(d+1)*132 + r + 8] = __half2float(p1.y)*inv[mb][1];
        }
    }
    __syncthreads();
    __half* aob = Og + (size_t)bh * HDIM * NPIX + m0;
    #pragma unroll
    for (int i = 0; i < 8; i++) {
        int idx = tid + i*128;
        int d = idx >> 5, seg = idx & 31;
        const float* src = &sT[d*132 + seg*4];
        uint2 p;
        p.x = pack_hf2(src[0], src[1]);
        p.y = pack_hf2(src[2], src[3]);
        *(uint2*)(aob + (size_t)d*NPIX + seg*4) = p;
    }
}

// ================= launch =================
extern "C" void kernel_launch(void* const* d_in, const int* in_sizes, int n_in,
                              void* d_out, int out_size) {
    const float* high  = (const float*)d_in[0];
    const float* low   = (const float*)d_in[1];
    const float* nhw   = (const float*)d_in[2];
    const float* nhb   = (const float*)d_in[3];
    const float* nlw   = (const float*)d_in[4];
    const float* nlb   = (const float*)d_in[5];
    const float* nfw   = (const float*)d_in[6];
    const float* nfb   = (const float*)d_in[7];
    const float* Wq    = (const float*)d_in[8];
    const float* Wk    = (const float*)d_in[9];
    const float* Wv    = (const float*)d_in[10];
    const float* Wproj = (const float*)d_in[11];
    const float* Wffn1 = (const float*)d_in[12];
    const float* Wffn2 = (const float*)d_in[13];
    const float* ga    = (const float*)d_in[14];
    const float* gf    = (const float*)d_in[15];
    float* out = (float*)d_out;

    float *x;
    __half *q, *k, *v, *ao, *mid, *whq, *whk, *whv, *whp, *wh1, *wh2;
    cudaGetSymbolAddress((void**)&q,   g_q);
    cudaGetSymbolAddress((void**)&k,   g_k);
    cudaGetSymbolAddress((void**)&v,   g_v);
    cudaGetSymbolAddress((void**)&ao,  g_ao);
    cudaGetSymbolAddress((void**)&x,   g_x);
    cudaGetSymbolAddress((void**)&mid, g_mid);
    cudaGetSymbolAddress((void**)&whq, g_whq);
    cudaGetSymbolAddress((void**)&whk, g_whk);
    cudaGetSymbolAddress((void**)&whv, g_whv);
    cudaGetSymbolAddress((void**)&whp, g_whp);
    cudaGetSymbolAddress((void**)&wh1, g_wh1);
    cudaGetSymbolAddress((void**)&wh2, g_wh2);

    const float scale = 0.17677669529663687f * 1.44269504088896340736f; // 1/sqrt(32)*log2e
    dim3 gg(NPIX/64, 1, BATCH);

    convert_weights<<<dim3(32, 6), 256>>>(Wq, Wk, Wv, Wproj, Wffn1, Wffn2, scale);
    stats_partial2<<<dim3(BATCH, 32, 2), 256>>>(high, low);

    gemm2<0,1,1,0><<<gg, 256>>>(high, nullptr, whq, whq, 64, CHIGH, CLOW,
                                nhw, nhb, 0, 32, nullptr, q, q, nullptr, nullptr);
    gemm2<0,1,2,0><<<gg, 256>>>(low, nullptr, whk, whv, 0, CLOW, CLOW,
                                nlw, nlb, 1, 32, nullptr, k, v, nullptr, nullptr);

    flash_mma<<<dim3(NPIX/128, BATCH*HEADS), 128>>>(q, k, v, ao);

    gemm2<2,2,1,1><<<gg, 256>>>(nullptr, ao, whp, whp, 64, CLOW, CLOW,
                                nullptr, nullptr, 0, 0, x, nullptr, nullptr, low, ga);

    gemm2<0,3,2,0><<<gg, 256>>>(x, nullptr, wh1, wh1, 128, CLOW, FFN,
                                nfw, nfb, 2, 64, nullptr, mid, mid, nullptr, nullptr);
    gemm2<2,2,1,0><<<gg, 256>>>(nullptr, mid, wh2, wh2, 64, FFN, CLOW,
                                nullptr, nullptr, 0, 0, out, nullptr, nullptr, x, gf);

    (void)in_sizes; (void)n_in; (void)out_size;
}

// round 13
// speedup vs baseline: 1.0292x; 1.0142x over previous
#include <cuda_runtime.h>
#include <cuda_fp16.h>
#include <math.h>
#include <stdint.h>

#define BATCH 4
#define NPIX  4096
#define CHIGH 256
#define CLOW  128
#define HEADS 4
#define HDIM  32
#define FFN   256

// ======================= helpers =======================
__device__ __forceinline__ uint32_t smem_u32(const void* p) {
    uint32_t a;
    asm("{ .reg .u64 t; cvta.to.shared.u64 t, %1; cvt.u32.u64 %0, t; }" : "=r"(a) : "l"(p));
    return a;
}

#define LDSM_X4(r0, r1, r2, r3, addr) \
    asm volatile("ldmatrix.sync.aligned.m8n8.x4.shared.b16 {%0,%1,%2,%3}, [%4];" \
        : "=r"(r0), "=r"(r1), "=r"(r2), "=r"(r3) : "r"(addr))
#define LDSM_X2(r0, r1, addr) \
    asm volatile("ldmatrix.sync.aligned.m8n8.x2.shared.b16 {%0,%1}, [%2];" \
        : "=r"(r0), "=r"(r1) : "r"(addr))
#define LDSM_X4_T(r0, r1, r2, r3, addr) \
    asm volatile("ldmatrix.sync.aligned.m8n8.x4.trans.shared.b16 {%0,%1,%2,%3}, [%4];" \
        : "=r"(r0), "=r"(r1), "=r"(r2), "=r"(r3) : "r"(addr))
#define LDSM_X2_T(r0, r1, addr) \
    asm volatile("ldmatrix.sync.aligned.m8n8.x2.trans.shared.b16 {%0,%1}, [%2];" \
        : "=r"(r0), "=r"(r1) : "r"(addr))
#define MMA16816(c, a, b) \
    asm volatile("mma.sync.aligned.m16n8k16.row.col.f32.f16.f16.f32 " \
        "{%0,%1,%2,%3}, {%4,%5,%6,%7}, {%8,%9}, {%0,%1,%2,%3};" \
        : "+f"((c)[0]), "+f"((c)[1]), "+f"((c)[2]), "+f"((c)[3]) \
        : "r"((a)[0]), "r"((a)[1]), "r"((a)[2]), "r"((a)[3]), "r"((b)[0]), "r"((b)[1]))
#define MMA16816H(c, a, b) \
    asm volatile("mma.sync.aligned.m16n8k16.row.col.f16.f16.f16.f16 " \
        "{%0,%1}, {%2,%3,%4,%5}, {%6,%7}, {%0,%1};" \
        : "+r"((c)[0]), "+r"((c)[1]) \
        : "r"((a)[0]), "r"((a)[1]), "r"((a)[2]), "r"((a)[3]), "r"((b)[0]), "r"((b)[1]))
#define EX2_F16X2(out, in) \
    asm("ex2.approx.f16x2 %0, %1;" : "=r"(out) : "r"(in))

__device__ __forceinline__ void cpa16(uint32_t dst, const void* src) {
    asm volatile("cp.async.ca.shared.global [%0], [%1], 16;" :: "r"(dst), "l"(src));
}
#define CP_COMMIT() asm volatile("cp.async.commit_group;" ::: "memory")
#define CP_WAIT0()  asm volatile("cp.async.wait_group 0;" ::: "memory")

__device__ __forceinline__ uint32_t pack_hf2(float a, float b) {
    __half2 h = __floats2half2_rn(a, b);
    return *(uint32_t*)&h;
}

// ======================= scratch =======================
__device__ __half g_q  [BATCH*CLOW *NPIX];   // [b][c][n], scale*log2e folded
__device__ __half g_k  [BATCH*CLOW *NPIX];
__device__ __half g_v  [BATCH*CLOW *NPIX];
__device__ __half g_ao [BATCH*CLOW *NPIX];
__device__ float  g_x  [BATCH*CLOW *NPIX];
__device__ __half g_mid[BATCH*FFN  *NPIX];
__device__ float g_part[3][BATCH][64][2];
__device__ __half g_whq[CLOW*CHIGH];
__device__ __half g_whk[CLOW*CLOW];
__device__ __half g_whv[CLOW*CLOW];
__device__ __half g_whp[CLOW*CLOW];
__device__ __half g_wh1[FFN*CLOW];
__device__ __half g_wh2[CLOW*FFN];

// ================= weight convert (fp32 -> fp16, scale folded for Wq) =================
__global__ void convert_weights(const float* __restrict__ Wq, const float* __restrict__ Wk,
                                const float* __restrict__ Wv, const float* __restrict__ Wp,
                                const float* __restrict__ W1, const float* __restrict__ W2,
                                float qscale) {
    int which = blockIdx.y;
    const float* src; __half* dst; int n; float a = 1.0f;
    switch (which) {
        case 0: src = Wq; dst = g_whq; n = CLOW*CHIGH; a = qscale; break;
        case 1: src = Wk; dst = g_whk; n = CLOW*CLOW;  break;
        case 2: src = Wv; dst = g_whv; n = CLOW*CLOW;  break;
        case 3: src = Wp; dst = g_whp; n = CLOW*CLOW;  break;
        case 4: src = W1; dst = g_wh1; n = FFN*CLOW;   break;
        default: src = W2; dst = g_wh2; n = CLOW*FFN;  break;
    }
    int i = (blockIdx.x * blockDim.x + threadIdx.x) * 4;
    if (i < n) {
        float4 v = *(const float4*)(src + i);
        uint2 p;
        p.x = pack_hf2(v.x*a, v.y*a);
        p.y = pack_hf2(v.z*a, v.w*a);
        *(uint2*)(dst + i) = p;
    }
}

// ================= GroupNorm stats partials (deterministic) =================
__global__ void stats_partial2(const float* __restrict__ high, const float* __restrict__ low) {
    int b = blockIdx.x, ch = blockIdx.y, z = blockIdx.z;
    int perSample = z ? CLOW*NPIX : CHIGH*NPIX;
    int perChunk  = perSample / 32;
    const float* p = (z ? low : high) + (size_t)b*perSample + (size_t)ch*perChunk;
    float s = 0.f, ss = 0.f;
    for (int i = threadIdx.x*4; i < perChunk; i += blockDim.x*4) {
        float4 v = *(const float4*)(p + i);
        s  += v.x + v.y + v.z + v.w;
        ss += v.x*v.x + v.y*v.y + v.z*v.z + v.w*v.w;
    }
    #pragma unroll
    for (int o = 16; o; o >>= 1) {
        s  += __shfl_xor_sync(0xffffffffu, s,  o);
        ss += __shfl_xor_sync(0xffffffffu, ss, o);
    }
    __shared__ float sh[2][8];
    int w = threadIdx.x >> 5;
    if ((threadIdx.x & 31) == 0) { sh[0][w] = s; sh[1][w] = ss; }
    __syncthreads();
    if (threadIdx.x == 0) {
        float S = 0.f, SS = 0.f;
        #pragma unroll
        for (int i = 0; i < 8; i++) { S += sh[0][i]; SS += sh[1][i]; }
        g_part[z][b][ch][0] = S; g_part[z][b][ch][1] = SS;
    }
}

// ================= dual-warpgroup TC GEMM, inlined stats + pipelined fp32 B =================
// INMODE: 0 = fp32 + groupnorm affine (stats reduced in-kernel), 2 = fp16 raw (cp.async)
// EP: 1 = f16 out; 2 = fp32 out = res + gamma*acc (+stats partials); 3 = gelu -> f16
template<int INMODE, int EP, int GTILES, int DOSTATS>
__global__ void __launch_bounds__(256, 2)
gemm2(const float* __restrict__ INf, const __half* __restrict__ INh,
      const __half* __restrict__ WA, const __half* __restrict__ WB, int gbase1,
      int K, int cw,
      const float* __restrict__ nw, const float* __restrict__ nbias, int sidx, int nchp,
      float* __restrict__ outf, __half* __restrict__ outhA, __half* __restrict__ outhB,
      const float* __restrict__ res, const float* __restrict__ gamma) {
    __shared__ __align__(16) __half sA[2][2][GTILES*64*40];
    __shared__ __align__(16) __half sB[2][32*72];
    __shared__ float s_stat[2];

    const int tid = threadIdx.x, warp = tid >> 5, lane = tid & 31;
    const int g = warp >> 2, wi = warp & 3, wt = tid & 127;
    const int b = blockIdx.z, n0 = blockIdx.x * 64;
    const __half* Wg = g ? WB : WA;
    __half* outh = g ? outhB : outhA;
    const int gbase = g ? gbase1 : 0;

    float mu = 0.f, rs = 0.f;
    if constexpr (INMODE == 0) {
        if (tid < 32) {
            float s = g_part[sidx][b][tid][0], ss = g_part[sidx][b][tid][1];
            if (nchp > 32) { s += g_part[sidx][b][tid+32][0]; ss += g_part[sidx][b][tid+32][1]; }
            #pragma unroll
            for (int o = 16; o; o >>= 1) {
                s  += __shfl_xor_sync(0xffffffffu, s,  o);
                ss += __shfl_xor_sync(0xffffffffu, ss, o);
            }
            if (tid == 0) {
                float cnt = (float)K * (float)NPIX;
                float m = s / cnt;
                float var = ss / cnt - m * m;
                s_stat[0] = m;
                s_stat[1] = rsqrtf(var + 1e-5f);
            }
        }
        __syncthreads();
        mu = s_stat[0]; rs = s_stat[1];
    }

    const int kB = tid >> 3, nsegB = tid & 7;

    auto stageA = [&](int k0, int bf) {
        #pragma unroll
        for (int it = 0; it < GTILES*2; it++) {
            int idx = wt + it*128;
            int c = idx >> 2, ch = idx & 3;
            cpa16(smem_u32(&sA[bf][g][c*40 + ch*8]),
                  Wg + (size_t)(gbase + c)*K + k0 + ch*8);
        }
    };
    auto loadB = [&](int k0, float4& ra, float4& rb) {
        const float* p = &INf[((size_t)b*K + k0 + kB)*NPIX + n0 + nsegB*8];
        ra = *(const float4*)p;
        rb = *(const float4*)(p + 4);
    };
    auto storeB = [&](int k0, int bf, const float4& ra, const float4& rb) {
        int kk = k0 + kB;
        float s0 = nw[kk]*rs, t0 = nbias[kk] - mu*s0;
        uint4 o;
        o.x = pack_hf2(ra.x*s0+t0, ra.y*s0+t0);
        o.y = pack_hf2(ra.z*s0+t0, ra.w*s0+t0);
        o.z = pack_hf2(rb.x*s0+t0, rb.y*s0+t0);
        o.w = pack_hf2(rb.z*s0+t0, rb.w*s0+t0);
        *(uint4*)&sB[bf][kB*72 + nsegB*8] = o;
    };
    auto stageB_async = [&](int k0, int bf) {
        cpa16(smem_u32(&sB[bf][kB*72 + nsegB*8]),
              &INh[((size_t)b*K + k0 + kB)*NPIX + n0 + nsegB*8]);
    };

    float acc[GTILES][8][4] = {};
    const int nch = K >> 5;

    stageA(0, 0);
    if constexpr (INMODE == 0) {
        float4 ra, rb;
        loadB(0, ra, rb);
        storeB(0, 0, ra, rb);
    } else {
        stageB_async(0, 0);
    }
    CP_COMMIT();

    for (int i = 0; i < nch; i++) {
        const int bf = i & 1;
        const bool more = (i + 1 < nch);

        float4 ra, rb;
        if (INMODE == 0 && more) loadB((i+1)*32, ra, rb);

        CP_WAIT0();
        __syncthreads();

        if (more) {
            stageA((i+1)*32, bf^1);
            if constexpr (INMODE == 2) stageB_async((i+1)*32, bf^1);
        }

        #pragma unroll
        for (int ct = 0; ct < GTILES; ct++) {
            uint32_t qa[2][4];
            #pragma unroll
            for (int kc = 0; kc < 2; kc++) {
                uint32_t addr = smem_u32(&sA[bf][g][(ct*64 + wi*16 + (lane & 15))*40
                                                    + kc*16 + (lane >> 4)*8]);
                LDSM_X4(qa[kc][0], qa[kc][1], qa[kc][2], qa[kc][3], addr);
            }
            #pragma unroll
            for (int nt = 0; nt < 8; nt++) {
                uint32_t b0[2], b1[2];
                uint32_t a0 = smem_u32(&sB[bf][(lane & 15)*72 + nt*8]);
                LDSM_X2_T(b0[0], b0[1], a0);
                LDSM_X2_T(b1[0], b1[1], a0 + 16*72*2);
                MMA16816(acc[ct][nt], qa[0], b0);
                MMA16816(acc[ct][nt], qa[1], b1);
            }
        }

        if (more) {
            if constexpr (INMODE == 0) storeB((i+1)*32, bf^1, ra, rb);
            CP_COMMIT();
        }
    }

    float s_s = 0.f, s_ss = 0.f;
    #pragma unroll
    for (int ct = 0; ct < GTILES; ct++) {
        #pragma unroll
        for (int nt = 0; nt < 8; nt++) {
            int n = nt*8 + (lane & 3)*2;
            int cA = gbase + ct*64 + wi*16 + (lane >> 2), cB = cA + 8;
            size_t oA = ((size_t)b*cw + cA)*NPIX + n0 + n;
            size_t oB = ((size_t)b*cw + cB)*NPIX + n0 + n;
            if constexpr (EP == 1) {
                *(uint32_t*)&outh[oA] = pack_hf2(acc[ct][nt][0], acc[ct][nt][1]);
                *(uint32_t*)&outh[oB] = pack_hf2(acc[ct][nt][2], acc[ct][nt][3]);
            } else if constexpr (EP == 2) {
                float gm = gamma[0];
                float2 rA = *(const float2*)&res[oA];
                float2 rB = *(const float2*)&res[oB];
                float v0 = rA.x + gm*acc[ct][nt][0], v1 = rA.y + gm*acc[ct][nt][1];
                float v2 = rB.x + gm*acc[ct][nt][2], v3 = rB.y + gm*acc[ct][nt][3];
                *(float2*)&outf[oA] = make_float2(v0, v1);
                *(float2*)&outf[oB] = make_float2(v2, v3);
                if (DOSTATS) {
                    s_s  += (v0 + v1) + (v2 + v3);
                    s_ss += v0*v0 + v1*v1 + v2*v2 + v3*v3;
                }
            } else {
                float v0 = acc[ct][nt][0], v1 = acc[ct][nt][1];
                float v2 = acc[ct][nt][2], v3 = acc[ct][nt][3];
                v0 = 0.5f*v0*(1.0f + erff(v0*0.70710678118654752f));
                v1 = 0.5f*v1*(1.0f + erff(v1*0.70710678118654752f));
                v2 = 0.5f*v2*(1.0f + erff(v2*0.70710678118654752f));
                v3 = 0.5f*v3*(1.0f + erff(v3*0.70710678118654752f));
                *(uint32_t*)&outh[oA] = pack_hf2(v0, v1);
                *(uint32_t*)&outh[oB] = pack_hf2(v2, v3);
            }
        }
    }
    if constexpr (DOSTATS) {
        #pragma unroll
        for (int o = 16; o; o >>= 1) {
            s_s  += __shfl_xor_sync(0xffffffffu, s_s,  o);
            s_ss += __shfl_xor_sync(0xffffffffu, s_ss, o);
        }
        __shared__ float shr[2][8];
        if (lane == 0) { shr[0][warp] = s_s; shr[1][warp] = s_ss; }
        __syncthreads();
        if (tid == 0) {
            float S = 0.f, SS = 0.f;
            #pragma unroll
            for (int i = 0; i < 8; i++) { S += shr[0][i]; SS += shr[1][i]; }
            g_part[2][b][blockIdx.x][0] = S; g_part[2][b][blockIdx.x][1] = SS;
        }
    }
}

// ================= flash attention (fp16 accum, occ4 via fp16 epilogue aliased in sQ) =================
#define QSTR 136
#define KVSTR 72

__device__ __forceinline__ void prefetch_kv(__half* sk, __half* sv,
        const __half* Kb, const __half* Vb, int n0, int tid) {
    #pragma unroll
    for (int i = 0; i < 2; i++) {
        int ch = tid + i * 128;
        int row = ch >> 3, col = ch & 7;
        cpa16(smem_u32(&sk[row*KVSTR + col*8]), Kb + (size_t)row*NPIX + n0 + col*8);
    }
    #pragma unroll
    for (int i = 0; i < 2; i++) {
        int ch = tid + i * 128;
        int row = ch >> 3, col = ch & 7;
        cpa16(smem_u32(&sv[row*KVSTR + col*8]), Vb + (size_t)row*NPIX + n0 + col*8);
    }
}

__global__ void __launch_bounds__(128, 4)
flash_mma(const __half* __restrict__ Qg, const __half* __restrict__ Kg,
          const __half* __restrict__ Vg, __half* __restrict__ Og) {
    __shared__ __align__(16) __half sQT[32*QSTR];   // Q tile; reused as fp16 output transpose
    __shared__ __align__(16) __half sK[2][32*KVSTR];
    __shared__ __align__(16) __half sV[2][40*KVSTR];

    const int tid = threadIdx.x, warp = tid >> 5, lane = tid & 31;
    const int bh = blockIdx.y, m0 = blockIdx.x * 128;
    const __half* Qb = Qg + (size_t)bh * HDIM * NPIX + m0;
    const __half* Kb = Kg + (size_t)bh * HDIM * NPIX;
    const __half* Vb = Vg + (size_t)bh * HDIM * NPIX;

    {
        int bfi = tid >> 6, row = 32 + ((tid >> 3) & 7), chk = tid & 7;
        float v = (row == 32) ? 1.0f : 0.0f;
        uint32_t hv = pack_hf2(v, v);
        uint4 q4 = make_uint4(hv, hv, hv, hv);
        *(uint4*)&sV[bfi][row*KVSTR + chk*8] = q4;
    }

    #pragma unroll
    for (int i = 0; i < 4; i++) {
        int ch = tid + i * 128;
        int row = ch >> 4, col = ch & 15;
        *(uint4*)&sQT[row*QSTR + col*8] = *(const uint4*)(Qb + (size_t)row*NPIX + col*8);
    }
    prefetch_kv(sK[0], sV[0], Kb, Vb, 0, tid);
    CP_COMMIT();
    __syncthreads();

    uint32_t qa[2][2][4];
    #pragma unroll
    for (int mb = 0; mb < 2; mb++)
        #pragma unroll
        for (int kc = 0; kc < 2; kc++) {
            uint32_t addr = smem_u32(&sQT[(kc*16 + ((lane >> 4) & 1)*8 + (lane & 7))*QSTR
                                          + warp*32 + mb*16 + ((lane >> 3) & 1)*8]);
            LDSM_X4_T(qa[mb][kc][0], qa[mb][kc][1], qa[mb][kc][2], qa[mb][kc][3], addr);
        }

    uint32_t Oc[2][5][2] = {};

    for (int nb = 0; nb < 64; nb++) {
        const int buf = nb & 1;
        CP_WAIT0();
        __syncthreads();
        if (nb < 63) {
            prefetch_kv(sK[buf^1], sV[buf^1], Kb, Vb, (nb+1)*64, tid);
            CP_COMMIT();
        }

        uint32_t pa[2][4][4];
        #pragma unroll
        for (int nt = 0; nt < 8; nt++) {
            uint32_t bk0[2], bk1[2];
            uint32_t a0 = smem_u32(&sK[buf][(lane & 15)*KVSTR + nt*8]);
            LDSM_X2_T(bk0[0], bk0[1], a0);
            LDSM_X2_T(bk1[0], bk1[1], a0 + 16*KVSTR*2);
            #pragma unroll
            for (int mb = 0; mb < 2; mb++) {
                uint32_t S[2] = {0u, 0u};
                MMA16816H(S, qa[mb][0], bk0);
                MMA16816H(S, qa[mb][1], bk1);
                EX2_F16X2(S[0], S[0]);
                EX2_F16X2(S[1], S[1]);
                pa[mb][nt >> 1][(nt & 1)*2 + 0] = S[0];
                pa[mb][nt >> 1][(nt & 1)*2 + 1] = S[1];
            }
        }

        #pragma unroll
        for (int kc = 0; kc < 4; kc++)
            #pragma unroll
            for (int dt = 0; dt < 5; dt++) {
                uint32_t vb[2];
                uint32_t addr = smem_u32(&sV[buf][(dt*8 + (lane & 7))*KVSTR
                                                  + kc*16 + ((lane >> 3) & 1)*8]);
                LDSM_X2(vb[0], vb[1], addr);
                MMA16816H(Oc[0][dt], pa[0][kc], vb);
                MMA16816H(Oc[1][dt], pa[1][kc], vb);
            }
    }

    float inv[2][2];
    #pragma unroll
    for (int mb = 0; mb < 2; mb++) {
        __half2 h0 = *(__half2*)&Oc[mb][4][0];
        __half2 h1 = *(__half2*)&Oc[mb][4][1];
        float l0 = __shfl_sync(0xffffffffu, __half2float(h0.x), lane & 28);
        float l1 = __shfl_sync(0xffffffffu, __half2float(h1.x), lane & 28);
        inv[mb][0] = 1.0f / l0;
        inv[mb][1] = 1.0f / l1;
    }

    // epilogue: fp16 transpose aliased over sQT (Q frags long since in registers)
    __syncthreads();
    #pragma unroll
    for (int mb = 0; mb < 2; mb++) {
        int r = warp*32 + mb*16 + (lane >> 2);
        #pragma unroll
        for (int dt = 0; dt < 4; dt++) {
            int d = dt*8 + (lane & 3)*2;
            __half2 p0 = *(__half2*)&Oc[mb][dt][0];
            __half2 p1 = *(__half2*)&Oc[mb][dt][1];
            sQT[(d+0)*QSTR + r    ] = __float2half(__half2float(p0.x)*inv[mb][0]);
            sQT[(d+1)*QSTR + r    ] = __float2half(__half2float(p0.y)*inv[mb][0]);
            sQT[(d+0)*QSTR + r + 8] = __float2half(__half2float(p1.x)*inv[mb][1]);
            sQT[(d+1)*QSTR + r + 8] = __float2half(__half2float(p1.y)*inv[mb][1]);
        }
    }
    __syncthreads();
    __half* aob = Og + (size_t)bh * HDIM * NPIX + m0;
    #pragma unroll
    for (int i = 0; i < 4; i++) {
        int idx = tid + i*128;
        int d = idx >> 4, seg = idx & 15;
        *(uint4*)(aob + (size_t)d*NPIX + seg*8) = *(const uint4*)&sQT[d*QSTR + seg*8];
    }
}

// ================= launch =================
extern "C" void kernel_launch(void* const* d_in, const int* in_sizes, int n_in,
                              void* d_out, int out_size) {
    const float* high  = (const float*)d_in[0];
    const float* low   = (const float*)d_in[1];
    const float* nhw   = (const float*)d_in[2];
    const float* nhb   = (const float*)d_in[3];
    const float* nlw   = (const float*)d_in[4];
    const float* nlb   = (const float*)d_in[5];
    const float* nfw   = (const float*)d_in[6];
    const float* nfb   = (const float*)d_in[7];
    const float* Wq    = (const float*)d_in[8];
    const float* Wk    = (const float*)d_in[9];
    const float* Wv    = (const float*)d_in[10];
    const float* Wproj = (const float*)d_in[11];
    const float* Wffn1 = (const float*)d_in[12];
    const float* Wffn2 = (const float*)d_in[13];
    const float* ga    = (const float*)d_in[14];
    const float* gf    = (const float*)d_in[15];
    float* out = (float*)d_out;

    float *x;
    __half *q, *k, *v, *ao, *mid, *whq, *whk, *whv, *whp, *wh1, *wh2;
    cudaGetSymbolAddress((void**)&q,   g_q);
    cudaGetSymbolAddress((void**)&k,   g_k);
    cudaGetSymbolAddress((void**)&v,   g_v);
    cudaGetSymbolAddress((void**)&ao,  g_ao);
    cudaGetSymbolAddress((void**)&x,   g_x);
    cudaGetSymbolAddress((void**)&mid, g_mid);
    cudaGetSymbolAddress((void**)&whq, g_whq);
    cudaGetSymbolAddress((void**)&whk, g_whk);
    cudaGetSymbolAddress((void**)&whv, g_whv);
    cudaGetSymbolAddress((void**)&whp, g_whp);
    cudaGetSymbolAddress((void**)&wh1, g_wh1);
    cudaGetSymbolAddress((void**)&wh2, g_wh2);

    const float scale = 0.17677669529663687f * 1.44269504088896340736f; // 1/sqrt(32)*log2e
    dim3 gg(NPIX/64, 1, BATCH);

    convert_weights<<<dim3(32, 6), 256>>>(Wq, Wk, Wv, Wproj, Wffn1, Wffn2, scale);
    stats_partial2<<<dim3(BATCH, 32, 2), 256>>>(high, low);

    gemm2<0,1,1,0><<<gg, 256>>>(high, nullptr, whq, whq, 64, CHIGH, CLOW,
                                nhw, nhb, 0, 32, nullptr, q, q, nullptr, nullptr);
    gemm2<0,1,2,0><<<gg, 256>>>(low, nullptr, whk, whv, 0, CLOW, CLOW,
                                nlw, nlb, 1, 32, nullptr, k, v, nullptr, nullptr);

    flash_mma<<<dim3(NPIX/128, BATCH*HEADS), 128>>>(q, k, v, ao);

    gemm2<2,2,1,1><<<gg, 256>>>(nullptr, ao, whp, whp, 64, CLOW, CLOW,
                                nullptr, nullptr, 0, 0, x, nullptr, nullptr, low, ga);

    gemm2<0,3,2,0><<<gg, 256>>>(x, nullptr, wh1, wh1, 128, CLOW, FFN,
                                nfw, nfb, 2, 64, nullptr, mid, mid, nullptr, nullptr);
    gemm2<2,2,1,0><<<gg, 256>>>(nullptr, mid, wh2, wh2, 64, FFN, CLOW,
                                nullptr, nullptr, 0, 0, out, nullptr, nullptr, x, gf);

    (void)in_sizes; (void)n_in; (void)out_size;
}

// round 14
// speedup vs baseline: 1.0425x; 1.0129x over previous
#include <cuda_runtime.h>
#include <cuda_fp16.h>
#include <math.h>
#include <stdint.h>

#define BATCH 4
#define NPIX  4096
#define CHIGH 256
#define CLOW  128
#define HEADS 4
#define HDIM  32
#define FFN   256

// ======================= helpers =======================
__device__ __forceinline__ uint32_t smem_u32(const void* p) {
    uint32_t a;
    asm("{ .reg .u64 t; cvta.to.shared.u64 t, %1; cvt.u32.u64 %0, t; }" : "=r"(a) : "l"(p));
    return a;
}

#define LDSM_X4(r0, r1, r2, r3, addr) \
    asm volatile("ldmatrix.sync.aligned.m8n8.x4.shared.b16 {%0,%1,%2,%3}, [%4];" \
        : "=r"(r0), "=r"(r1), "=r"(r2), "=r"(r3) : "r"(addr))
#define LDSM_X2(r0, r1, addr) \
    asm volatile("ldmatrix.sync.aligned.m8n8.x2.shared.b16 {%0,%1}, [%2];" \
        : "=r"(r0), "=r"(r1) : "r"(addr))
#define LDSM_X4_T(r0, r1, r2, r3, addr) \
    asm volatile("ldmatrix.sync.aligned.m8n8.x4.trans.shared.b16 {%0,%1,%2,%3}, [%4];" \
        : "=r"(r0), "=r"(r1), "=r"(r2), "=r"(r3) : "r"(addr))
#define LDSM_X2_T(r0, r1, addr) \
    asm volatile("ldmatrix.sync.aligned.m8n8.x2.trans.shared.b16 {%0,%1}, [%2];" \
        : "=r"(r0), "=r"(r1) : "r"(addr))
#define MMA16816(c, a, b) \
    asm volatile("mma.sync.aligned.m16n8k16.row.col.f32.f16.f16.f32 " \
        "{%0,%1,%2,%3}, {%4,%5,%6,%7}, {%8,%9}, {%0,%1,%2,%3};" \
        : "+f"((c)[0]), "+f"((c)[1]), "+f"((c)[2]), "+f"((c)[3]) \
        : "r"((a)[0]), "r"((a)[1]), "r"((a)[2]), "r"((a)[3]), "r"((b)[0]), "r"((b)[1]))
#define MMA16816H(c, a, b) \
    asm volatile("mma.sync.aligned.m16n8k16.row.col.f16.f16.f16.f16 " \
        "{%0,%1}, {%2,%3,%4,%5}, {%6,%7}, {%0,%1};" \
        : "+r"((c)[0]), "+r"((c)[1]) \
        : "r"((a)[0]), "r"((a)[1]), "r"((a)[2]), "r"((a)[3]), "r"((b)[0]), "r"((b)[1]))
#define EX2_F16X2(out, in) \
    asm("ex2.approx.f16x2 %0, %1;" : "=r"(out) : "r"(in))

__device__ __forceinline__ void cpa16(uint32_t dst, const void* src) {
    asm volatile("cp.async.ca.shared.global [%0], [%1], 16;" :: "r"(dst), "l"(src));
}
#define CP_COMMIT() asm volatile("cp.async.commit_group;" ::: "memory")
#define CP_WAIT0()  asm volatile("cp.async.wait_group 0;" ::: "memory")

__device__ __forceinline__ uint32_t pack_hf2(float a, float b) {
    __half2 h = __floats2half2_rn(a, b);
    return *(uint32_t*)&h;
}
__device__ __forceinline__ uint32_t hadd2u(uint32_t a, uint32_t b) {
    __half2 r = __hadd2(*(__half2*)&a, *(__half2*)&b);
    return *(uint32_t*)&r;
}

// ======================= scratch =======================
__device__ __half g_q  [BATCH*CLOW *NPIX];   // [b][c][n], scale*log2e folded
__device__ __half g_k  [BATCH*CLOW *NPIX];
__device__ __half g_v  [BATCH*CLOW *NPIX];
__device__ __half g_ao [BATCH*CLOW *NPIX];
__device__ float  g_x  [BATCH*CLOW *NPIX];
__device__ __half g_mid[BATCH*FFN  *NPIX];
__device__ float g_part[3][BATCH][64][2];
__device__ __half g_whq[CLOW*CHIGH];
__device__ __half g_whk[CLOW*CLOW];
__device__ __half g_whv[CLOW*CLOW];
__device__ __half g_whp[CLOW*CLOW];
__device__ __half g_wh1[FFN*CLOW];
__device__ __half g_wh2[CLOW*FFN];

// ================= fused prep: weight convert + input stats partials =================
__global__ void prep_kernel(const float* __restrict__ high, const float* __restrict__ low,
                            const float* __restrict__ Wq, const float* __restrict__ Wk,
                            const float* __restrict__ Wv, const float* __restrict__ Wp,
                            const float* __restrict__ W1, const float* __restrict__ W2,
                            float qscale) {
    int bx = blockIdx.x;
    if (bx < 192) {
        // weight convert: which = bx>>5, chunk = bx&31
        int which = bx >> 5, sub = bx & 31;
        const float* src; __half* dst; int n; float a = 1.0f;
        switch (which) {
            case 0: src = Wq; dst = g_whq; n = CLOW*CHIGH; a = qscale; break;
            case 1: src = Wk; dst = g_whk; n = CLOW*CLOW;  break;
            case 2: src = Wv; dst = g_whv; n = CLOW*CLOW;  break;
            case 3: src = Wp; dst = g_whp; n = CLOW*CLOW;  break;
            case 4: src = W1; dst = g_wh1; n = FFN*CLOW;   break;
            default: src = W2; dst = g_wh2; n = CLOW*FFN;  break;
        }
        int i = (sub * 256 + threadIdx.x) * 4;
        if (i < n) {
            float4 v = *(const float4*)(src + i);
            uint2 p;
            p.x = pack_hf2(v.x*a, v.y*a);
            p.y = pack_hf2(v.z*a, v.w*a);
            *(uint2*)(dst + i) = p;
        }
    } else {
        // stats partials: t in [0,256): z = t>>7, b = (t>>5)&3, ch = t&31
        int t = bx - 192;
        int z = t >> 7, b = (t >> 5) & 3, ch = t & 31;
        int perSample = z ? CLOW*NPIX : CHIGH*NPIX;
        int perChunk  = perSample / 32;
        const float* p = (z ? low : high) + (size_t)b*perSample + (size_t)ch*perChunk;
        float s = 0.f, ss = 0.f;
        for (int i = threadIdx.x*4; i < perChunk; i += 256*4) {
            float4 v = *(const float4*)(p + i);
            s  += v.x + v.y + v.z + v.w;
            ss += v.x*v.x + v.y*v.y + v.z*v.z + v.w*v.w;
        }
        #pragma unroll
        for (int o = 16; o; o >>= 1) {
            s  += __shfl_xor_sync(0xffffffffu, s,  o);
            ss += __shfl_xor_sync(0xffffffffu, ss, o);
        }
        __shared__ float sh[2][8];
        int w = threadIdx.x >> 5;
        if ((threadIdx.x & 31) == 0) { sh[0][w] = s; sh[1][w] = ss; }
        __syncthreads();
        if (threadIdx.x == 0) {
            float S = 0.f, SS = 0.f;
            #pragma unroll
            for (int i = 0; i < 8; i++) { S += sh[0][i]; SS += sh[1][i]; }
            g_part[z][b][ch][0] = S; g_part[z][b][ch][1] = SS;
        }
    }
}

// ================= fused Q + KV projections (one launch, blockIdx.y dispatch) =================
__global__ void __launch_bounds__(256, 2)
gemm_qkv(const float* __restrict__ high, const float* __restrict__ low,
         const __half* __restrict__ whq, const __half* __restrict__ whk,
         const __half* __restrict__ whv,
         const float* __restrict__ nhw, const float* __restrict__ nhb,
         const float* __restrict__ nlw, const float* __restrict__ nlb,
         __half* __restrict__ qo, __half* __restrict__ ko, __half* __restrict__ vo) {
    __shared__ __align__(16) __half sA[2][2][2*64*40];
    __shared__ __align__(16) __half sB[2][32*72];
    __shared__ float s_stat[2];

    const int tid = threadIdx.x, warp = tid >> 5, lane = tid & 31;
    const int g = warp >> 2, wi = warp & 3, wt = tid & 127;
    const int b = blockIdx.z, n0 = blockIdx.x * 64;
    const bool isQ = (blockIdx.y == 0);

    const float* INf = isQ ? high : low;
    const int K = isQ ? CHIGH : CLOW;
    const int sidx = isQ ? 0 : 1;
    const float* nw    = isQ ? nhw : nlw;
    const float* nbias = isQ ? nhb : nlb;
    const int ntiles = isQ ? 1 : 2;
    const __half* Wg = isQ ? whq : (g ? whv : whk);
    const int gbase = (isQ && g) ? 64 : 0;
    __half* outh = isQ ? qo : (g ? vo : ko);

    float mu, rs;
    {
        if (tid < 32) {
            float s = g_part[sidx][b][tid][0], ss = g_part[sidx][b][tid][1];
            #pragma unroll
            for (int o = 16; o; o >>= 1) {
                s  += __shfl_xor_sync(0xffffffffu, s,  o);
                ss += __shfl_xor_sync(0xffffffffu, ss, o);
            }
            if (tid == 0) {
                float cnt = (float)K * (float)NPIX;
                float m = s / cnt;
                float var = ss / cnt - m * m;
                s_stat[0] = m;
                s_stat[1] = rsqrtf(var + 1e-5f);
            }
        }
        __syncthreads();
        mu = s_stat[0]; rs = s_stat[1];
    }

    const int kB = tid >> 3, nsegB = tid & 7;

    auto stageA = [&](int k0, int bf) {
        #pragma unroll
        for (int it = 0; it < 4; it++) {
            if (it < ntiles*2) {
                int idx = wt + it*128;
                int c = idx >> 2, ch = idx & 3;
                cpa16(smem_u32(&sA[bf][g][c*40 + ch*8]),
                      Wg + (size_t)(gbase + c)*K + k0 + ch*8);
            }
        }
    };
    auto loadB = [&](int k0, float4& ra, float4& rb) {
        const float* p = &INf[((size_t)b*K + k0 + kB)*NPIX + n0 + nsegB*8];
        ra = *(const float4*)p;
        rb = *(const float4*)(p + 4);
    };
    auto storeB = [&](int k0, int bf, const float4& ra, const float4& rb) {
        int kk = k0 + kB;
        float s0 = nw[kk]*rs, t0 = nbias[kk] - mu*s0;
        uint4 o;
        o.x = pack_hf2(ra.x*s0+t0, ra.y*s0+t0);
        o.y = pack_hf2(ra.z*s0+t0, ra.w*s0+t0);
        o.z = pack_hf2(rb.x*s0+t0, rb.y*s0+t0);
        o.w = pack_hf2(rb.z*s0+t0, rb.w*s0+t0);
        *(uint4*)&sB[bf][kB*72 + nsegB*8] = o;
    };

    float acc[2][8][4] = {};
    const int nch = K >> 5;

    stageA(0, 0);
    {
        float4 ra, rb;
        loadB(0, ra, rb);
        storeB(0, 0, ra, rb);
    }
    CP_COMMIT();

    for (int i = 0; i < nch; i++) {
        const int bf = i & 1;
        const bool more = (i + 1 < nch);

        float4 ra, rb;
        if (more) loadB((i+1)*32, ra, rb);

        CP_WAIT0();
        __syncthreads();

        if (more) stageA((i+1)*32, bf^1);

        #pragma unroll
        for (int ct = 0; ct < 2; ct++) {
            if (ct < ntiles) {
                uint32_t qa[2][4];
                #pragma unroll
                for (int kc = 0; kc < 2; kc++) {
                    uint32_t addr = smem_u32(&sA[bf][g][(ct*64 + wi*16 + (lane & 15))*40
                                                        + kc*16 + (lane >> 4)*8]);
                    LDSM_X4(qa[kc][0], qa[kc][1], qa[kc][2], qa[kc][3], addr);
                }
                #pragma unroll
                for (int nt = 0; nt < 8; nt++) {
                    uint32_t b0[2], b1[2];
                    uint32_t a0 = smem_u32(&sB[bf][(lane & 15)*72 + nt*8]);
                    LDSM_X2_T(b0[0], b0[1], a0);
                    LDSM_X2_T(b1[0], b1[1], a0 + 16*72*2);
                    MMA16816(acc[ct][nt], qa[0], b0);
                    MMA16816(acc[ct][nt], qa[1], b1);
                }
            }
        }

        if (more) {
            storeB((i+1)*32, bf^1, ra, rb);
            CP_COMMIT();
        }
    }

    #pragma unroll
    for (int ct = 0; ct < 2; ct++) {
        if (ct < ntiles) {
            #pragma unroll
            for (int nt = 0; nt < 8; nt++) {
                int n = nt*8 + (lane & 3)*2;
                int cA = gbase + ct*64 + wi*16 + (lane >> 2), cB = cA + 8;
                size_t oA = ((size_t)b*CLOW + cA)*NPIX + n0 + n;
                size_t oB = ((size_t)b*CLOW + cB)*NPIX + n0 + n;
                *(uint32_t*)&outh[oA] = pack_hf2(acc[ct][nt][0], acc[ct][nt][1]);
                *(uint32_t*)&outh[oB] = pack_hf2(acc[ct][nt][2], acc[ct][nt][3]);
            }
        }
    }
}

// ================= general TC GEMM (proj/ffn path; R13-proven) =================
// INMODE: 0 = fp32 + groupnorm affine (stats inlined), 2 = fp16 raw (cp.async)
// EP: 2 = fp32 out = res + gamma*acc (+stats partials); 3 = gelu -> f16
template<int INMODE, int EP, int GTILES, int DOSTATS>
__global__ void __launch_bounds__(256, 2)
gemm2(const float* __restrict__ INf, const __half* __restrict__ INh,
      const __half* __restrict__ WA, const __half* __restrict__ WB, int gbase1,
      int K, int cw,
      const float* __restrict__ nw, const float* __restrict__ nbias, int sidx, int nchp,
      float* __restrict__ outf, __half* __restrict__ outhA, __half* __restrict__ outhB,
      const float* __restrict__ res, const float* __restrict__ gamma) {
    __shared__ __align__(16) __half sA[2][2][GTILES*64*40];
    __shared__ __align__(16) __half sB[2][32*72];
    __shared__ float s_stat[2];

    const int tid = threadIdx.x, warp = tid >> 5, lane = tid & 31;
    const int g = warp >> 2, wi = warp & 3, wt = tid & 127;
    const int b = blockIdx.z, n0 = blockIdx.x * 64;
    const __half* Wg = g ? WB : WA;
    __half* outh = g ? outhB : outhA;
    const int gbase = g ? gbase1 : 0;

    float mu = 0.f, rs = 0.f;
    if constexpr (INMODE == 0) {
        if (tid < 32) {
            float s = g_part[sidx][b][tid][0], ss = g_part[sidx][b][tid][1];
            if (nchp > 32) { s += g_part[sidx][b][tid+32][0]; ss += g_part[sidx][b][tid+32][1]; }
            #pragma unroll
            for (int o = 16; o; o >>= 1) {
                s  += __shfl_xor_sync(0xffffffffu, s,  o);
                ss += __shfl_xor_sync(0xffffffffu, ss, o);
            }
            if (tid == 0) {
                float cnt = (float)K * (float)NPIX;
                float m = s / cnt;
                float var = ss / cnt - m * m;
                s_stat[0] = m;
                s_stat[1] = rsqrtf(var + 1e-5f);
            }
        }
        __syncthreads();
        mu = s_stat[0]; rs = s_stat[1];
    }

    const int kB = tid >> 3, nsegB = tid & 7;

    auto stageA = [&](int k0, int bf) {
        #pragma unroll
        for (int it = 0; it < GTILES*2; it++) {
            int idx = wt + it*128;
            int c = idx >> 2, ch = idx & 3;
            cpa16(smem_u32(&sA[bf][g][c*40 + ch*8]),
                  Wg + (size_t)(gbase + c)*K + k0 + ch*8);
        }
    };
    auto loadB = [&](int k0, float4& ra, float4& rb) {
        const float* p = &INf[((size_t)b*K + k0 + kB)*NPIX + n0 + nsegB*8];
        ra = *(const float4*)p;
        rb = *(const float4*)(p + 4);
    };
    auto storeB = [&](int k0, int bf, const float4& ra, const float4& rb) {
        int kk = k0 + kB;
        float s0 = nw[kk]*rs, t0 = nbias[kk] - mu*s0;
        uint4 o;
        o.x = pack_hf2(ra.x*s0+t0, ra.y*s0+t0);
        o.y = pack_hf2(ra.z*s0+t0, ra.w*s0+t0);
        o.z = pack_hf2(rb.x*s0+t0, rb.y*s0+t0);
        o.w = pack_hf2(rb.z*s0+t0, rb.w*s0+t0);
        *(uint4*)&sB[bf][kB*72 + nsegB*8] = o;
    };
    auto stageB_async = [&](int k0, int bf) {
        cpa16(smem_u32(&sB[bf][kB*72 + nsegB*8]),
              &INh[((size_t)b*K + k0 + kB)*NPIX + n0 + nsegB*8]);
    };

    float acc[GTILES][8][4] = {};
    const int nch = K >> 5;

    stageA(0, 0);
    if constexpr (INMODE == 0) {
        float4 ra, rb;
        loadB(0, ra, rb);
        storeB(0, 0, ra, rb);
    } else {
        stageB_async(0, 0);
    }
    CP_COMMIT();

    for (int i = 0; i < nch; i++) {
        const int bf = i & 1;
        const bool more = (i + 1 < nch);

        float4 ra, rb;
        if (INMODE == 0 && more) loadB((i+1)*32, ra, rb);

        CP_WAIT0();
        __syncthreads();

        if (more) {
            stageA((i+1)*32, bf^1);
            if constexpr (INMODE == 2) stageB_async((i+1)*32, bf^1);
        }

        #pragma unroll
        for (int ct = 0; ct < GTILES; ct++) {
            uint32_t qa[2][4];
            #pragma unroll
            for (int kc = 0; kc < 2; kc++) {
                uint32_t addr = smem_u32(&sA[bf][g][(ct*64 + wi*16 + (lane & 15))*40
                                                    + kc*16 + (lane >> 4)*8]);
                LDSM_X4(qa[kc][0], qa[kc][1], qa[kc][2], qa[kc][3], addr);
            }
            #pragma unroll
            for (int nt = 0; nt < 8; nt++) {
                uint32_t b0[2], b1[2];
                uint32_t a0 = smem_u32(&sB[bf][(lane & 15)*72 + nt*8]);
                LDSM_X2_T(b0[0], b0[1], a0);
                LDSM_X2_T(b1[0], b1[1], a0 + 16*72*2);
                MMA16816(acc[ct][nt], qa[0], b0);
                MMA16816(acc[ct][nt], qa[1], b1);
            }
        }

        if (more) {
            if constexpr (INMODE == 0) storeB((i+1)*32, bf^1, ra, rb);
            CP_COMMIT();
        }
    }

    float s_s = 0.f, s_ss = 0.f;
    #pragma unroll
    for (int ct = 0; ct < GTILES; ct++) {
        #pragma unroll
        for (int nt = 0; nt < 8; nt++) {
            int n = nt*8 + (lane & 3)*2;
            int cA = gbase + ct*64 + wi*16 + (lane >> 2), cB = cA + 8;
            size_t oA = ((size_t)b*cw + cA)*NPIX + n0 + n;
            size_t oB = ((size_t)b*cw + cB)*NPIX + n0 + n;
            if constexpr (EP == 2) {
                float gm = gamma[0];
                float2 rA = *(const float2*)&res[oA];
                float2 rB = *(const float2*)&res[oB];
                float v0 = rA.x + gm*acc[ct][nt][0], v1 = rA.y + gm*acc[ct][nt][1];
                float v2 = rB.x + gm*acc[ct][nt][2], v3 = rB.y + gm*acc[ct][nt][3];
                *(float2*)&outf[oA] = make_float2(v0, v1);
                *(float2*)&outf[oB] = make_float2(v2, v3);
                if (DOSTATS) {
                    s_s  += (v0 + v1) + (v2 + v3);
                    s_ss += v0*v0 + v1*v1 + v2*v2 + v3*v3;
                }
            } else {
                float v0 = acc[ct][nt][0], v1 = acc[ct][nt][1];
                float v2 = acc[ct][nt][2], v3 = acc[ct][nt][3];
                v0 = 0.5f*v0*(1.0f + erff(v0*0.70710678118654752f));
                v1 = 0.5f*v1*(1.0f + erff(v1*0.70710678118654752f));
                v2 = 0.5f*v2*(1.0f + erff(v2*0.70710678118654752f));
                v3 = 0.5f*v3*(1.0f + erff(v3*0.70710678118654752f));
                *(uint32_t*)&outh[oA] = pack_hf2(v0, v1);
                *(uint32_t*)&outh[oB] = pack_hf2(v2, v3);
            }
        }
    }
    if constexpr (DOSTATS) {
        #pragma unroll
        for (int o = 16; o; o >>= 1) {
            s_s  += __shfl_xor_sync(0xffffffffu, s_s,  o);
            s_ss += __shfl_xor_sync(0xffffffffu, s_ss, o);
        }
        __shared__ float shr[2][8];
        if (lane == 0) { shr[0][warp] = s_s; shr[1][warp] = s_ss; }
        __syncthreads();
        if (tid == 0) {
            float S = 0.f, SS = 0.f;
            #pragma unroll
            for (int i = 0; i < 8; i++) { S += shr[0][i]; SS += shr[1][i]; }
            g_part[2][b][blockIdx.x][0] = S; g_part[2][b][blockIdx.x][1] = SS;
        }
    }
}

// ================= flash attention (fp16 accum; l via HADD2 of P frags) =================
#define QSTR 136
#define KVSTR 72

__device__ __forceinline__ void prefetch_kv(__half* sk, __half* sv,
        const __half* Kb, const __half* Vb, int n0, int tid) {
    #pragma unroll
    for (int i = 0; i < 2; i++) {
        int ch = tid + i * 128;
        int row = ch >> 3, col = ch & 7;
        cpa16(smem_u32(&sk[row*KVSTR + col*8]), Kb + (size_t)row*NPIX + n0 + col*8);
    }
    #pragma unroll
    for (int i = 0; i < 2; i++) {
        int ch = tid + i * 128;
        int row = ch >> 3, col = ch & 7;
        cpa16(smem_u32(&sv[row*KVSTR + col*8]), Vb + (size_t)row*NPIX + n0 + col*8);
    }
}

__global__ void __launch_bounds__(128, 4)
flash_mma(const __half* __restrict__ Qg, const __half* __restrict__ Kg,
          const __half* __restrict__ Vg, __half* __restrict__ Og) {
    __shared__ __align__(16) __half sQT[32*QSTR];   // Q tile; reused as fp16 output transpose
    __shared__ __align__(16) __half sK[2][32*KVSTR];
    __shared__ __align__(16) __half sV[2][32*KVSTR];

    const int tid = threadIdx.x, warp = tid >> 5, lane = tid & 31;
    const int bh = blockIdx.y, m0 = blockIdx.x * 128;
    const __half* Qb = Qg + (size_t)bh * HDIM * NPIX + m0;
    const __half* Kb = Kg + (size_t)bh * HDIM * NPIX;
    const __half* Vb = Vg + (size_t)bh * HDIM * NPIX;

    #pragma unroll
    for (int i = 0; i < 4; i++) {
        int ch = tid + i * 128;
        int row = ch >> 4, col = ch & 15;
        *(uint4*)&sQT[row*QSTR + col*8] = *(const uint4*)(Qb + (size_t)row*NPIX + col*8);
    }
    prefetch_kv(sK[0], sV[0], Kb, Vb, 0, tid);
    CP_COMMIT();
    __syncthreads();

    uint32_t qa[2][2][4];
    #pragma unroll
    for (int mb = 0; mb < 2; mb++)
        #pragma unroll
        for (int kc = 0; kc < 2; kc++) {
            uint32_t addr = smem_u32(&sQT[(kc*16 + ((lane >> 4) & 1)*8 + (lane & 7))*QSTR
                                          + warp*32 + mb*16 + ((lane >> 3) & 1)*8]);
            LDSM_X4_T(qa[mb][kc][0], qa[mb][kc][1], qa[mb][kc][2], qa[mb][kc][3], addr);
        }

    uint32_t Oc[2][4][2] = {};
    float lrow[2][2] = {};

    for (int nb = 0; nb < 64; nb++) {
        const int buf = nb & 1;
        CP_WAIT0();
        __syncthreads();
        if (nb < 63) {
            prefetch_kv(sK[buf^1], sV[buf^1], Kb, Vb, (nb+1)*64, tid);
            CP_COMMIT();
        }

        // ---- S = Q K^T (fp16 accum), in-place EX2 -> P fragments ----
        uint32_t pa[2][4][4];
        #pragma unroll
        for (int nt = 0; nt < 8; nt++) {
            uint32_t bk0[2], bk1[2];
            uint32_t a0 = smem_u32(&sK[buf][(lane & 15)*KVSTR + nt*8]);
            LDSM_X2_T(bk0[0], bk0[1], a0);
            LDSM_X2_T(bk1[0], bk1[1], a0 + 16*KVSTR*2);
            #pragma unroll
            for (int mb = 0; mb < 2; mb++) {
                uint32_t S[2] = {0u, 0u};
                MMA16816H(S, qa[mb][0], bk0);
                MMA16816H(S, qa[mb][1], bk1);
                EX2_F16X2(S[0], S[0]);
                EX2_F16X2(S[1], S[1]);
                pa[mb][nt >> 1][(nt & 1)*2 + 0] = S[0];
                pa[mb][nt >> 1][(nt & 1)*2 + 1] = S[1];
            }
        }

        // ---- l-sum via HADD2 of P A-frags (rows r: elems [0],[2]; rows r+8: [1],[3]) ----
        #pragma unroll
        for (int mb = 0; mb < 2; mb++) {
            uint32_t h0 = hadd2u(pa[mb][0][0], pa[mb][0][2]);
            uint32_t h1 = hadd2u(pa[mb][0][1], pa[mb][0][3]);
            #pragma unroll
            for (int kc = 1; kc < 4; kc++) {
                h0 = hadd2u(h0, hadd2u(pa[mb][kc][0], pa[mb][kc][2]));
                h1 = hadd2u(h1, hadd2u(pa[mb][kc][1], pa[mb][kc][3]));
            }
            float2 f0 = __half22float2(*(__half2*)&h0);
            float2 f1 = __half22float2(*(__half2*)&h1);
            lrow[mb][0] += f0.x + f0.y;
            lrow[mb][1] += f1.x + f1.y;
        }

        // ---- O += P V (fp16 accum) ----
        #pragma unroll
        for (int kc = 0; kc < 4; kc++)
            #pragma unroll
            for (int dt = 0; dt < 4; dt++) {
                uint32_t vb[2];
                uint32_t addr = smem_u32(&sV[buf][(dt*8 + (lane & 7))*KVSTR
                                                  + kc*16 + ((lane >> 3) & 1)*8]);
                LDSM_X2(vb[0], vb[1], addr);
                MMA16816H(Oc[0][dt], pa[0][kc], vb);
                MMA16816H(Oc[1][dt], pa[1][kc], vb);
            }
    }

    // reduce l across the 4 lanes of each row quad
    float inv[2][2];
    #pragma unroll
    for (int mb = 0; mb < 2; mb++)
        #pragma unroll
        for (int j = 0; j < 2; j++) {
            float v = lrow[mb][j];
            v += __shfl_xor_sync(0xffffffffu, v, 1);
            v += __shfl_xor_sync(0xffffffffu, v, 2);
            inv[mb][j] = 1.0f / v;
        }

    // epilogue: fp16 transpose aliased over sQT
    __syncthreads();
    #pragma unroll
    for (int mb = 0; mb < 2; mb++) {
        int r = warp*32 + mb*16 + (lane >> 2);
        #pragma unroll
        for (int dt = 0; dt < 4; dt++) {
            int d = dt*8 + (lane & 3)*2;
            __half2 p0 = *(__half2*)&Oc[mb][dt][0];
            __half2 p1 = *(__half2*)&Oc[mb][dt][1];
            sQT[(d+0)*QSTR + r    ] = __float2half(__half2float(p0.x)*inv[mb][0]);
            sQT[(d+1)*QSTR + r    ] = __float2half(__half2float(p0.y)*inv[mb][0]);
            sQT[(d+0)*QSTR + r + 8] = __float2half(__half2float(p1.x)*inv[mb][1]);
            sQT[(d+1)*QSTR + r + 8] = __float2half(__half2float(p1.y)*inv[mb][1]);
        }
    }
    __syncthreads();
    __half* aob = Og + (size_t)bh * HDIM * NPIX + m0;
    #pragma unroll
    for (int i = 0; i < 4; i++) {
        int idx = tid + i*128;
        int d = idx >> 4, seg = idx & 15;
        *(uint4*)(aob + (size_t)d*NPIX + seg*8) = *(const uint4*)&sQT[d*QSTR + seg*8];
    }
}

// ================= launch =================
extern "C" void kernel_launch(void* const* d_in, const int* in_sizes, int n_in,
                              void* d_out, int out_size) {
    const float* high  = (const float*)d_in[0];
    const float* low   = (const float*)d_in[1];
    const float* nhw   = (const float*)d_in[2];
    const float* nhb   = (const float*)d_in[3];
    const float* nlw   = (const float*)d_in[4];
    const float* nlb   = (const float*)d_in[5];
    const float* nfw   = (const float*)d_in[6];
    const float* nfb   = (const float*)d_in[7];
    const float* Wq    = (const float*)d_in[8];
    const float* Wk    = (const float*)d_in[9];
    const float* Wv    = (const float*)d_in[10];
    const float* Wproj = (const float*)d_in[11];
    const float* Wffn1 = (const float*)d_in[12];
    const float* Wffn2 = (const float*)d_in[13];
    const float* ga    = (const float*)d_in[14];
    const float* gf    = (const float*)d_in[15];
    float* out = (float*)d_out;

    float *x;
    __half *q, *k, *v, *ao, *mid, *whq, *whk, *whv, *whp, *wh1, *wh2;
    cudaGetSymbolAddress((void**)&q,   g_q);
    cudaGetSymbolAddress((void**)&k,   g_k);
    cudaGetSymbolAddress((void**)&v,   g_v);
    cudaGetSymbolAddress((void**)&ao,  g_ao);
    cudaGetSymbolAddress((void**)&x,   g_x);
    cudaGetSymbolAddress((void**)&mid, g_mid);
    cudaGetSymbolAddress((void**)&whq, g_whq);
    cudaGetSymbolAddress((void**)&whk, g_whk);
    cudaGetSymbolAddress((void**)&whv, g_whv);
    cudaGetSymbolAddress((void**)&whp, g_whp);
    cudaGetSymbolAddress((void**)&wh1, g_wh1);
    cudaGetSymbolAddress((void**)&wh2, g_wh2);

    const float scale = 0.17677669529663687f * 1.44269504088896340736f; // 1/sqrt(32)*log2e
    dim3 gg(NPIX/64, 1, BATCH);

    prep_kernel<<<448, 256>>>(high, low, Wq, Wk, Wv, Wproj, Wffn1, Wffn2, scale);

    gemm_qkv<<<dim3(NPIX/64, 2, BATCH), 256>>>(high, low, whq, whk, whv,
                                               nhw, nhb, nlw, nlb, q, k, v);

    flash_mma<<<dim3(NPIX/128, BATCH*HEADS), 128>>>(q, k, v, ao);

    gemm2<2,2,1,1><<<gg, 256>>>(nullptr, ao, whp, whp, 64, CLOW, CLOW,
                                nullptr, nullptr, 0, 0, x, nullptr, nullptr, low, ga);

    gemm2<0,3,2,0><<<gg, 256>>>(x, nullptr, wh1, wh1, 128, CLOW, FFN,
                                nfw, nfb, 2, 64, nullptr, mid, mid, nullptr, nullptr);
    gemm2<2,2,1,0><<<gg, 256>>>(nullptr, mid, wh2, wh2, 64, FFN, CLOW,
                                nullptr, nullptr, 0, 0, out, nullptr, nullptr, x, gf);

    (void)in_sizes; (void)n_in; (void)out_size;
}

// round 15
// speedup vs baseline: 1.0673x; 1.0238x over previous
#include <cuda_runtime.h>
#include <cuda_fp16.h>
#include <math.h>
#include <stdint.h>

#define BATCH 4
#define NPIX  4096
#define CHIGH 256
#define CLOW  128
#define HEADS 4
#define HDIM  32
#define FFN   256

// ======================= helpers =======================
__device__ __forceinline__ uint32_t smem_u32(const void* p) {
    uint32_t a;
    asm("{ .reg .u64 t; cvta.to.shared.u64 t, %1; cvt.u32.u64 %0, t; }" : "=r"(a) : "l"(p));
    return a;
}

#define LDSM_X4(r0, r1, r2, r3, addr) \
    asm volatile("ldmatrix.sync.aligned.m8n8.x4.shared.b16 {%0,%1,%2,%3}, [%4];" \
        : "=r"(r0), "=r"(r1), "=r"(r2), "=r"(r3) : "r"(addr))
#define LDSM_X2(r0, r1, addr) \
    asm volatile("ldmatrix.sync.aligned.m8n8.x2.shared.b16 {%0,%1}, [%2];" \
        : "=r"(r0), "=r"(r1) : "r"(addr))
#define LDSM_X4_T(r0, r1, r2, r3, addr) \
    asm volatile("ldmatrix.sync.aligned.m8n8.x4.trans.shared.b16 {%0,%1,%2,%3}, [%4];" \
        : "=r"(r0), "=r"(r1), "=r"(r2), "=r"(r3) : "r"(addr))
#define LDSM_X2_T(r0, r1, addr) \
    asm volatile("ldmatrix.sync.aligned.m8n8.x2.trans.shared.b16 {%0,%1}, [%2];" \
        : "=r"(r0), "=r"(r1) : "r"(addr))
#define MMA16816(c, a, b) \
    asm volatile("mma.sync.aligned.m16n8k16.row.col.f32.f16.f16.f32 " \
        "{%0,%1,%2,%3}, {%4,%5,%6,%7}, {%8,%9}, {%0,%1,%2,%3};" \
        : "+f"((c)[0]), "+f"((c)[1]), "+f"((c)[2]), "+f"((c)[3]) \
        : "r"((a)[0]), "r"((a)[1]), "r"((a)[2]), "r"((a)[3]), "r"((b)[0]), "r"((b)[1]))
#define MMA16816H(c, a, b) \
    asm volatile("mma.sync.aligned.m16n8k16.row.col.f16.f16.f16.f16 " \
        "{%0,%1}, {%2,%3,%4,%5}, {%6,%7}, {%0,%1};" \
        : "+r"((c)[0]), "+r"((c)[1]) \
        : "r"((a)[0]), "r"((a)[1]), "r"((a)[2]), "r"((a)[3]), "r"((b)[0]), "r"((b)[1]))
#define EX2_F16X2(out, in) \
    asm("ex2.approx.f16x2 %0, %1;" : "=r"(out) : "r"(in))

__device__ __forceinline__ void cpa16(uint32_t dst, const void* src) {
    asm volatile("cp.async.ca.shared.global [%0], [%1], 16;" :: "r"(dst), "l"(src));
}
#define CP_COMMIT() asm volatile("cp.async.commit_group;" ::: "memory")
#define CP_WAIT0()  asm volatile("cp.async.wait_group 0;" ::: "memory")

__device__ __forceinline__ uint32_t pack_hf2(float a, float b) {
    __half2 h = __floats2half2_rn(a, b);
    return *(uint32_t*)&h;
}
__device__ __forceinline__ uint32_t hadd2u(uint32_t a, uint32_t b) {
    __half2 r = __hadd2(*(__half2*)&a, *(__half2*)&b);
    return *(uint32_t*)&r;
}

// ======================= scratch =======================
__device__ __half g_q  [BATCH*CLOW *NPIX];   // [b][c][n], scale*log2e folded
__device__ __half g_k  [BATCH*CLOW *NPIX];
__device__ __half g_v  [BATCH*CLOW *NPIX];
__device__ __half g_ao [BATCH*CLOW *NPIX];
__device__ float  g_x  [BATCH*CLOW *NPIX];
__device__ float g_part[3][BATCH][64][2];
__device__ __half g_whq[CLOW*CHIGH];
__device__ __half g_whk[CLOW*CLOW];
__device__ __half g_whv[CLOW*CLOW];
__device__ __half g_whp[CLOW*CLOW];
__device__ __half g_wh1[FFN*CLOW];
__device__ __half g_wh2[CLOW*FFN];

// ================= fused prep: weight convert + input stats partials =================
__global__ void prep_kernel(const float* __restrict__ high, const float* __restrict__ low,
                            const float* __restrict__ Wq, const float* __restrict__ Wk,
                            const float* __restrict__ Wv, const float* __restrict__ Wp,
                            const float* __restrict__ W1, const float* __restrict__ W2,
                            float qscale) {
    int bx = blockIdx.x;
    if (bx < 192) {
        int which = bx >> 5, sub = bx & 31;
        const float* src; __half* dst; int n; float a = 1.0f;
        switch (which) {
            case 0: src = Wq; dst = g_whq; n = CLOW*CHIGH; a = qscale; break;
            case 1: src = Wk; dst = g_whk; n = CLOW*CLOW;  break;
            case 2: src = Wv; dst = g_whv; n = CLOW*CLOW;  break;
            case 3: src = Wp; dst = g_whp; n = CLOW*CLOW;  break;
            case 4: src = W1; dst = g_wh1; n = FFN*CLOW;   break;
            default: src = W2; dst = g_wh2; n = CLOW*FFN;  break;
        }
        int i = (sub * 256 + threadIdx.x) * 4;
        if (i < n) {
            float4 v = *(const float4*)(src + i);
            uint2 p;
            p.x = pack_hf2(v.x*a, v.y*a);
            p.y = pack_hf2(v.z*a, v.w*a);
            *(uint2*)(dst + i) = p;
        }
    } else {
        int t = bx - 192;
        int z = t >> 7, b = (t >> 5) & 3, ch = t & 31;
        int perSample = z ? CLOW*NPIX : CHIGH*NPIX;
        int perChunk  = perSample / 32;
        const float* p = (z ? low : high) + (size_t)b*perSample + (size_t)ch*perChunk;
        float s = 0.f, ss = 0.f;
        for (int i = threadIdx.x*4; i < perChunk; i += 256*4) {
            float4 v = *(const float4*)(p + i);
            s  += v.x + v.y + v.z + v.w;
            ss += v.x*v.x + v.y*v.y + v.z*v.z + v.w*v.w;
        }
        #pragma unroll
        for (int o = 16; o; o >>= 1) {
            s  += __shfl_xor_sync(0xffffffffu, s,  o);
            ss += __shfl_xor_sync(0xffffffffu, ss, o);
        }
        __shared__ float sh[2][8];
        int w = threadIdx.x >> 5;
        if ((threadIdx.x & 31) == 0) { sh[0][w] = s; sh[1][w] = ss; }
        __syncthreads();
        if (threadIdx.x == 0) {
            float S = 0.f, SS = 0.f;
            #pragma unroll
            for (int i = 0; i < 8; i++) { S += sh[0][i]; SS += sh[1][i]; }
            g_part[z][b][ch][0] = S; g_part[z][b][ch][1] = SS;
        }
    }
}

// ================= fused Q + KV projections (R14-proven) =================
__global__ void __launch_bounds__(256, 2)
gemm_qkv(const float* __restrict__ high, const float* __restrict__ low,
         const __half* __restrict__ whq, const __half* __restrict__ whk,
         const __half* __restrict__ whv,
         const float* __restrict__ nhw, const float* __restrict__ nhb,
         const float* __restrict__ nlw, const float* __restrict__ nlb,
         __half* __restrict__ qo, __half* __restrict__ ko, __half* __restrict__ vo) {
    __shared__ __align__(16) __half sA[2][2][2*64*40];
    __shared__ __align__(16) __half sB[2][32*72];
    __shared__ float s_stat[2];

    const int tid = threadIdx.x, warp = tid >> 5, lane = tid & 31;
    const int g = warp >> 2, wi = warp & 3, wt = tid & 127;
    const int b = blockIdx.z, n0 = blockIdx.x * 64;
    const bool isQ = (blockIdx.y == 0);

    const float* INf = isQ ? high : low;
    const int K = isQ ? CHIGH : CLOW;
    const int sidx = isQ ? 0 : 1;
    const float* nw    = isQ ? nhw : nlw;
    const float* nbias = isQ ? nhb : nlb;
    const int ntiles = isQ ? 1 : 2;
    const __half* Wg = isQ ? whq : (g ? whv : whk);
    const int gbase = (isQ && g) ? 64 : 0;
    __half* outh = isQ ? qo : (g ? vo : ko);

    float mu, rs;
    {
        if (tid < 32) {
            float s = g_part[sidx][b][tid][0], ss = g_part[sidx][b][tid][1];
            #pragma unroll
            for (int o = 16; o; o >>= 1) {
                s  += __shfl_xor_sync(0xffffffffu, s,  o);
                ss += __shfl_xor_sync(0xffffffffu, ss, o);
            }
            if (tid == 0) {
                float cnt = (float)K * (float)NPIX;
                float m = s / cnt;
                float var = ss / cnt - m * m;
                s_stat[0] = m;
                s_stat[1] = rsqrtf(var + 1e-5f);
            }
        }
        __syncthreads();
        mu = s_stat[0]; rs = s_stat[1];
    }

    const int kB = tid >> 3, nsegB = tid & 7;

    auto stageA = [&](int k0, int bf) {
        #pragma unroll
        for (int it = 0; it < 4; it++) {
            if (it < ntiles*2) {
                int idx = wt + it*128;
                int c = idx >> 2, ch = idx & 3;
                cpa16(smem_u32(&sA[bf][g][c*40 + ch*8]),
                      Wg + (size_t)(gbase + c)*K + k0 + ch*8);
            }
        }
    };
    auto loadB = [&](int k0, float4& ra, float4& rb) {
        const float* p = &INf[((size_t)b*K + k0 + kB)*NPIX + n0 + nsegB*8];
        ra = *(const float4*)p;
        rb = *(const float4*)(p + 4);
    };
    auto storeB = [&](int k0, int bf, const float4& ra, const float4& rb) {
        int kk = k0 + kB;
        float s0 = nw[kk]*rs, t0 = nbias[kk] - mu*s0;
        uint4 o;
        o.x = pack_hf2(ra.x*s0+t0, ra.y*s0+t0);
        o.y = pack_hf2(ra.z*s0+t0, ra.w*s0+t0);
        o.z = pack_hf2(rb.x*s0+t0, rb.y*s0+t0);
        o.w = pack_hf2(rb.z*s0+t0, rb.w*s0+t0);
        *(uint4*)&sB[bf][kB*72 + nsegB*8] = o;
    };

    float acc[2][8][4] = {};
    const int nch = K >> 5;

    stageA(0, 0);
    {
        float4 ra, rb;
        loadB(0, ra, rb);
        storeB(0, 0, ra, rb);
    }
    CP_COMMIT();

    for (int i = 0; i < nch; i++) {
        const int bf = i & 1;
        const bool more = (i + 1 < nch);

        float4 ra, rb;
        if (more) loadB((i+1)*32, ra, rb);

        CP_WAIT0();
        __syncthreads();

        if (more) stageA((i+1)*32, bf^1);

        #pragma unroll
        for (int ct = 0; ct < 2; ct++) {
            if (ct < ntiles) {
                uint32_t qa[2][4];
                #pragma unroll
                for (int kc = 0; kc < 2; kc++) {
                    uint32_t addr = smem_u32(&sA[bf][g][(ct*64 + wi*16 + (lane & 15))*40
                                                        + kc*16 + (lane >> 4)*8]);
                    LDSM_X4(qa[kc][0], qa[kc][1], qa[kc][2], qa[kc][3], addr);
                }
                #pragma unroll
                for (int nt = 0; nt < 8; nt++) {
                    uint32_t b0[2], b1[2];
                    uint32_t a0 = smem_u32(&sB[bf][(lane & 15)*72 + nt*8]);
                    LDSM_X2_T(b0[0], b0[1], a0);
                    LDSM_X2_T(b1[0], b1[1], a0 + 16*72*2);
                    MMA16816(acc[ct][nt], qa[0], b0);
                    MMA16816(acc[ct][nt], qa[1], b1);
                }
            }
        }

        if (more) {
            storeB((i+1)*32, bf^1, ra, rb);
            CP_COMMIT();
        }
    }

    #pragma unroll
    for (int ct = 0; ct < 2; ct++) {
        if (ct < ntiles) {
            #pragma unroll
            for (int nt = 0; nt < 8; nt++) {
                int n = nt*8 + (lane & 3)*2;
                int cA = gbase + ct*64 + wi*16 + (lane >> 2), cB = cA + 8;
                size_t oA = ((size_t)b*CLOW + cA)*NPIX + n0 + n;
                size_t oB = ((size_t)b*CLOW + cB)*NPIX + n0 + n;
                *(uint32_t*)&outh[oA] = pack_hf2(acc[ct][nt][0], acc[ct][nt][1]);
                *(uint32_t*)&outh[oB] = pack_hf2(acc[ct][nt][2], acc[ct][nt][3]);
            }
        }
    }
}

// ================= proj GEMM: x = low + ga*Wp@ao, + x-stats partials (R14-proven) =================
__global__ void __launch_bounds__(256, 2)
gemm_proj(const __half* __restrict__ INh, const __half* __restrict__ W,
          float* __restrict__ outf, const float* __restrict__ res,
          const float* __restrict__ gamma) {
    __shared__ __align__(16) __half sA[2][2][64*40];
    __shared__ __align__(16) __half sB[2][32*72];

    const int tid = threadIdx.x, warp = tid >> 5, lane = tid & 31;
    const int g = warp >> 2, wi = warp & 3, wt = tid & 127;
    const int b = blockIdx.z, n0 = blockIdx.x * 64;
    const int gbase = g ? 64 : 0;

    const int kB = tid >> 3, nsegB = tid & 7;

    auto stageA = [&](int k0, int bf) {
        #pragma unroll
        for (int it = 0; it < 2; it++) {
            int idx = wt + it*128;
            int c = idx >> 2, ch = idx & 3;
            cpa16(smem_u32(&sA[bf][g][c*40 + ch*8]),
                  W + (size_t)(gbase + c)*CLOW + k0 + ch*8);
        }
    };
    auto stageB = [&](int k0, int bf) {
        cpa16(smem_u32(&sB[bf][kB*72 + nsegB*8]),
              &INh[((size_t)b*CLOW + k0 + kB)*NPIX + n0 + nsegB*8]);
    };

    float acc[8][4] = {};

    stageA(0, 0); stageB(0, 0); CP_COMMIT();
    for (int i = 0; i < 4; i++) {
        const int bf = i & 1;
        CP_WAIT0();
        __syncthreads();
        if (i + 1 < 4) { stageA((i+1)*32, bf^1); stageB((i+1)*32, bf^1); CP_COMMIT(); }

        uint32_t qa[2][4];
        #pragma unroll
        for (int kc = 0; kc < 2; kc++) {
            uint32_t addr = smem_u32(&sA[bf][g][(wi*16 + (lane & 15))*40
                                                + kc*16 + (lane >> 4)*8]);
            LDSM_X4(qa[kc][0], qa[kc][1], qa[kc][2], qa[kc][3], addr);
        }
        #pragma unroll
        for (int nt = 0; nt < 8; nt++) {
            uint32_t b0[2], b1[2];
            uint32_t a0 = smem_u32(&sB[bf][(lane & 15)*72 + nt*8]);
            LDSM_X2_T(b0[0], b0[1], a0);
            LDSM_X2_T(b1[0], b1[1], a0 + 16*72*2);
            MMA16816(acc[nt], qa[0], b0);
            MMA16816(acc[nt], qa[1], b1);
        }
    }

    float gm = gamma[0];
    float s_s = 0.f, s_ss = 0.f;
    #pragma unroll
    for (int nt = 0; nt < 8; nt++) {
        int n = nt*8 + (lane & 3)*2;
        int cA = gbase + wi*16 + (lane >> 2), cB = cA + 8;
        size_t oA = ((size_t)b*CLOW + cA)*NPIX + n0 + n;
        size_t oB = ((size_t)b*CLOW + cB)*NPIX + n0 + n;
        float2 rA = *(const float2*)&res[oA];
        float2 rB = *(const float2*)&res[oB];
        float v0 = rA.x + gm*acc[nt][0], v1 = rA.y + gm*acc[nt][1];
        float v2 = rB.x + gm*acc[nt][2], v3 = rB.y + gm*acc[nt][3];
        *(float2*)&outf[oA] = make_float2(v0, v1);
        *(float2*)&outf[oB] = make_float2(v2, v3);
        s_s  += (v0 + v1) + (v2 + v3);
        s_ss += v0*v0 + v1*v1 + v2*v2 + v3*v3;
    }
    #pragma unroll
    for (int o = 16; o; o >>= 1) {
        s_s  += __shfl_xor_sync(0xffffffffu, s_s,  o);
        s_ss += __shfl_xor_sync(0xffffffffu, s_ss, o);
    }
    __shared__ float shr[2][8];
    if (lane == 0) { shr[0][warp] = s_s; shr[1][warp] = s_ss; }
    __syncthreads();
    if (tid == 0) {
        float S = 0.f, SS = 0.f;
        #pragma unroll
        for (int i = 0; i < 8; i++) { S += shr[0][i]; SS += shr[1][i]; }
        g_part[2][b][blockIdx.x][0] = S; g_part[2][b][blockIdx.x][1] = SS;
    }
}

// ================= fused FFN: out = x + gf * W2 @ gelu(W1 @ norm(x)) =================
// phase 1: mid[256][n0:64] -> sM smem tile; phase 2: W2 @ sM + residual
#define SMSTR 264
__global__ void __launch_bounds__(256)
fused_ffn(const float* __restrict__ xin,
          const __half* __restrict__ W1, const __half* __restrict__ W2,
          const float* __restrict__ nw, const float* __restrict__ nbias,
          float* __restrict__ outf, const float* __restrict__ gamma) {
    extern __shared__ __align__(16) char smemRaw[];
    __half* sA = (__half*)smemRaw;              // phase1: [2 buf][2 grp][5120]; phase2 alias sW[2][5120]
    __half* sB = (__half*)(smemRaw + 40960);    // [2][2304]
    __half* sM = (__half*)(smemRaw + 50176);    // [64][SMSTR]
    __shared__ float s_stat[2];

    const int tid = threadIdx.x, warp = tid >> 5, lane = tid & 31;
    const int g = warp >> 2, wi = warp & 3, wt = tid & 127;
    const int b = blockIdx.z, n0 = blockIdx.x * 64;

    float mu, rs;
    {
        if (tid < 32) {
            float s = g_part[2][b][tid][0] + g_part[2][b][tid+32][0];
            float ss = g_part[2][b][tid][1] + g_part[2][b][tid+32][1];
            #pragma unroll
            for (int o = 16; o; o >>= 1) {
                s  += __shfl_xor_sync(0xffffffffu, s,  o);
                ss += __shfl_xor_sync(0xffffffffu, ss, o);
            }
            if (tid == 0) {
                float cnt = (float)CLOW * (float)NPIX;
                float m = s / cnt;
                float var = ss / cnt - m * m;
                s_stat[0] = m;
                s_stat[1] = rsqrtf(var + 1e-5f);
            }
        }
        __syncthreads();
        mu = s_stat[0]; rs = s_stat[1];
    }

    const int kB = tid >> 3, nsegB = tid & 7;
    const int gbase = g ? 128 : 0;

    auto stageA = [&](int k0, int bf) {
        #pragma unroll
        for (int it = 0; it < 4; it++) {
            int idx = wt + it*128;
            int c = idx >> 2, ch = idx & 3;
            cpa16(smem_u32(&sA[(bf*2 + g)*5120 + c*40 + ch*8]),
                  W1 + (size_t)(gbase + c)*CLOW + k0 + ch*8);
        }
    };
    auto loadB = [&](int k0, float4& ra, float4& rb) {
        const float* p = &xin[((size_t)b*CLOW + k0 + kB)*NPIX + n0 + nsegB*8];
        ra = *(const float4*)p;
        rb = *(const float4*)(p + 4);
    };
    auto storeB = [&](int k0, int bf, const float4& ra, const float4& rb) {
        int kk = k0 + kB;
        float s0 = nw[kk]*rs, t0 = nbias[kk] - mu*s0;
        uint4 o;
        o.x = pack_hf2(ra.x*s0+t0, ra.y*s0+t0);
        o.y = pack_hf2(ra.z*s0+t0, ra.w*s0+t0);
        o.z = pack_hf2(rb.x*s0+t0, rb.y*s0+t0);
        o.w = pack_hf2(rb.z*s0+t0, rb.w*s0+t0);
        *(uint4*)&sB[bf*2304 + kB*72 + nsegB*8] = o;
    };

    // ---- phase 1: 256-channel gelu(W1 @ norm(x)) -> sM ----
    float acc[2][8][4] = {};
    stageA(0, 0);
    {
        float4 ra, rb;
        loadB(0, ra, rb);
        storeB(0, 0, ra, rb);
    }
    CP_COMMIT();

    for (int i = 0; i < 4; i++) {
        const int bf = i & 1;
        const bool more = (i + 1 < 4);
        float4 ra, rb;
        if (more) loadB((i+1)*32, ra, rb);
        CP_WAIT0();
        __syncthreads();
        if (more) stageA((i+1)*32, bf^1);

        #pragma unroll
        for (int ct = 0; ct < 2; ct++) {
            uint32_t qa[2][4];
            #pragma unroll
            for (int kc = 0; kc < 2; kc++) {
                uint32_t addr = smem_u32(&sA[(bf*2 + g)*5120 + (ct*64 + wi*16 + (lane & 15))*40
                                             + kc*16 + (lane >> 4)*8]);
                LDSM_X4(qa[kc][0], qa[kc][1], qa[kc][2], qa[kc][3], addr);
            }
            #pragma unroll
            for (int nt = 0; nt < 8; nt++) {
                uint32_t b0[2], b1[2];
                uint32_t a0 = smem_u32(&sB[bf*2304 + (lane & 15)*72 + nt*8]);
                LDSM_X2_T(b0[0], b0[1], a0);
                LDSM_X2_T(b1[0], b1[1], a0 + 16*72*2);
                MMA16816(acc[ct][nt], qa[0], b0);
                MMA16816(acc[ct][nt], qa[1], b1);
            }
        }

        if (more) {
            storeB((i+1)*32, bf^1, ra, rb);
            CP_COMMIT();
        }
    }

    // gelu -> sM[n][c] (c = channel = k of phase 2)
    #pragma unroll
    for (int ct = 0; ct < 2; ct++) {
        #pragma unroll
        for (int nt = 0; nt < 8; nt++) {
            int n = nt*8 + (lane & 3)*2;
            int cA = gbase + ct*64 + wi*16 + (lane >> 2), cB = cA + 8;
            float v0 = acc[ct][nt][0], v1 = acc[ct][nt][1];
            float v2 = acc[ct][nt][2], v3 = acc[ct][nt][3];
            v0 = 0.5f*v0*(1.0f + erff(v0*0.70710678118654752f));
            v1 = 0.5f*v1*(1.0f + erff(v1*0.70710678118654752f));
            v2 = 0.5f*v2*(1.0f + erff(v2*0.70710678118654752f));
            v3 = 0.5f*v3*(1.0f + erff(v3*0.70710678118654752f));
            sM[(n+0)*SMSTR + cA] = __float2half(v0);
            sM[(n+1)*SMSTR + cA] = __float2half(v1);
            sM[(n+0)*SMSTR + cB] = __float2half(v2);
            sM[(n+1)*SMSTR + cB] = __float2half(v3);
        }
    }
    __syncthreads();

    // ---- phase 2: out = x + gf * W2 @ sM ----
    // sW aliases sA region (phase-1 reads complete). 8 warps x 16 c-rows = 128.
    __half* sW = sA;
    auto stageW = [&](int k0, int bf) {
        #pragma unroll
        for (int it = 0; it < 2; it++) {
            int idx = tid + it*256;
            int c = idx >> 2, ch = idx & 3;
            cpa16(smem_u32(&sW[bf*5120 + c*40 + ch*8]),
                  W2 + (size_t)c*FFN + k0 + ch*8);
        }
    };

    float acc2[8][4] = {};
    stageW(0, 0); CP_COMMIT();
    for (int i = 0; i < 8; i++) {
        const int bf = i & 1;
        CP_WAIT0();
        __syncthreads();
        if (i + 1 < 8) { stageW((i+1)*32, bf^1); CP_COMMIT(); }

        uint32_t qa[2][4];
        #pragma unroll
        for (int kc = 0; kc < 2; kc++) {
            uint32_t addr = smem_u32(&sW[bf*5120 + (warp*16 + (lane & 15))*40
                                         + kc*16 + (lane >> 4)*8]);
            LDSM_X4(qa[kc][0], qa[kc][1], qa[kc][2], qa[kc][3], addr);
        }
        #pragma unroll
        for (int nt = 0; nt < 8; nt++) {
            uint32_t b0[2], b1[2];
            uint32_t a0 = smem_u32(&sM[(nt*8 + (lane & 7))*SMSTR + i*32
                                       + ((lane >> 3) & 1)*8]);
            LDSM_X2(b0[0], b0[1], a0);
            LDSM_X2(b1[0], b1[1], a0 + 32);   // +16 halves = k16 chunk 1
            MMA16816(acc2[nt], qa[0], b0);
            MMA16816(acc2[nt], qa[1], b1);
        }
    }

    float gm = gamma[0];
    #pragma unroll
    for (int nt = 0; nt < 8; nt++) {
        int n = nt*8 + (lane & 3)*2;
        int cA = warp*16 + (lane >> 2), cB = cA + 8;
        size_t oA = ((size_t)b*CLOW + cA)*NPIX + n0 + n;
        size_t oB = ((size_t)b*CLOW + cB)*NPIX + n0 + n;
        float2 rA = *(const float2*)&xin[oA];
        float2 rB = *(const float2*)&xin[oB];
        *(float2*)&outf[oA] = make_float2(rA.x + gm*acc2[nt][0], rA.y + gm*acc2[nt][1]);
        *(float2*)&outf[oB] = make_float2(rB.x + gm*acc2[nt][2], rB.y + gm*acc2[nt][3]);
    }
}

// ================= flash attention (R14-proven) =================
#define QSTR 136
#define KVSTR 72

__device__ __forceinline__ void prefetch_kv(__half* sk, __half* sv,
        const __half* Kb, const __half* Vb, int n0, int tid) {
    #pragma unroll
    for (int i = 0; i < 2; i++) {
        int ch = tid + i * 128;
        int row = ch >> 3, col = ch & 7;
        cpa16(smem_u32(&sk[row*KVSTR + col*8]), Kb + (size_t)row*NPIX + n0 + col*8);
    }
    #pragma unroll
    for (int i = 0; i < 2; i++) {
        int ch = tid + i * 128;
        int row = ch >> 3, col = ch & 7;
        cpa16(smem_u32(&sv[row*KVSTR + col*8]), Vb + (size_t)row*NPIX + n0 + col*8);
    }
}

__global__ void __launch_bounds__(128, 4)
flash_mma(const __half* __restrict__ Qg, const __half* __restrict__ Kg,
          const __half* __restrict__ Vg, __half* __restrict__ Og) {
    __shared__ __align__(16) __half sQT[32*QSTR];
    __shared__ __align__(16) __half sK[2][32*KVSTR];
    __shared__ __align__(16) __half sV[2][32*KVSTR];

    const int tid = threadIdx.x, warp = tid >> 5, lane = tid & 31;
    const int bh = blockIdx.y, m0 = blockIdx.x * 128;
    const __half* Qb = Qg + (size_t)bh * HDIM * NPIX + m0;
    const __half* Kb = Kg + (size_t)bh * HDIM * NPIX;
    const __half* Vb = Vg + (size_t)bh * HDIM * NPIX;

    #pragma unroll
    for (int i = 0; i < 4; i++) {
        int ch = tid + i * 128;
        int row = ch >> 4, col = ch & 15;
        *(uint4*)&sQT[row*QSTR + col*8] = *(const uint4*)(Qb + (size_t)row*NPIX + col*8);
    }
    prefetch_kv(sK[0], sV[0], Kb, Vb, 0, tid);
    CP_COMMIT();
    __syncthreads();

    uint32_t qa[2][2][4];
    #pragma unroll
    for (int mb = 0; mb < 2; mb++)
        #pragma unroll
        for (int kc = 0; kc < 2; kc++) {
            uint32_t addr = smem_u32(&sQT[(kc*16 + ((lane >> 4) & 1)*8 + (lane & 7))*QSTR
                                          + warp*32 + mb*16 + ((lane >> 3) & 1)*8]);
            LDSM_X4_T(qa[mb][kc][0], qa[mb][kc][1], qa[mb][kc][2], qa[mb][kc][3], addr);
        }

    uint32_t Oc[2][4][2] = {};
    float lrow[2][2] = {};

    for (int nb = 0; nb < 64; nb++) {
        const int buf = nb & 1;
        CP_WAIT0();
        __syncthreads();
        if (nb < 63) {
            prefetch_kv(sK[buf^1], sV[buf^1], Kb, Vb, (nb+1)*64, tid);
            CP_COMMIT();
        }

        uint32_t pa[2][4][4];
        #pragma unroll
        for (int nt = 0; nt < 8; nt++) {
            uint32_t bk0[2], bk1[2];
            uint32_t a0 = smem_u32(&sK[buf][(lane & 15)*KVSTR + nt*8]);
            LDSM_X2_T(bk0[0], bk0[1], a0);
            LDSM_X2_T(bk1[0], bk1[1], a0 + 16*KVSTR*2);
            #pragma unroll
            for (int mb = 0; mb < 2; mb++) {
                uint32_t S[2] = {0u, 0u};
                MMA16816H(S, qa[mb][0], bk0);
                MMA16816H(S, qa[mb][1], bk1);
                EX2_F16X2(S[0], S[0]);
                EX2_F16X2(S[1], S[1]);
                pa[mb][nt >> 1][(nt & 1)*2 + 0] = S[0];
                pa[mb][nt >> 1][(nt & 1)*2 + 1] = S[1];
            }
        }

        #pragma unroll
        for (int mb = 0; mb < 2; mb++) {
            uint32_t h0 = hadd2u(pa[mb][0][0], pa[mb][0][2]);
            uint32_t h1 = hadd2u(pa[mb][0][1], pa[mb][0][3]);
            #pragma unroll
            for (int kc = 1; kc < 4; kc++) {
                h0 = hadd2u(h0, hadd2u(pa[mb][kc][0], pa[mb][kc][2]));
                h1 = hadd2u(h1, hadd2u(pa[mb][kc][1], pa[mb][kc][3]));
            }
            float2 f0 = __half22float2(*(__half2*)&h0);
            float2 f1 = __half22float2(*(__half2*)&h1);
            lrow[mb][0] += f0.x + f0.y;
            lrow[mb][1] += f1.x + f1.y;
        }

        #pragma unroll
        for (int kc = 0; kc < 4; kc++)
            #pragma unroll
            for (int dt = 0; dt < 4; dt++) {
                uint32_t vb[2];
                uint32_t addr = smem_u32(&sV[buf][(dt*8 + (lane & 7))*KVSTR
                                                  + kc*16 + ((lane >> 3) & 1)*8]);
                LDSM_X2(vb[0], vb[1], addr);
                MMA16816H(Oc[0][dt], pa[0][kc], vb);
                MMA16816H(Oc[1][dt], pa[1][kc], vb);
            }
    }

    float inv[2][2];
    #pragma unroll
    for (int mb = 0; mb < 2; mb++)
        #pragma unroll
        for (int j = 0; j < 2; j++) {
            float v = lrow[mb][j];
            v += __shfl_xor_sync(0xffffffffu, v, 1);
            v += __shfl_xor_sync(0xffffffffu, v, 2);
            inv[mb][j] = 1.0f / v;
        }

    __syncthreads();
    #pragma unroll
    for (int mb = 0; mb < 2; mb++) {
        int r = warp*32 + mb*16 + (lane >> 2);
        #pragma unroll
        for (int dt = 0; dt < 4; dt++) {
            int d = dt*8 + (lane & 3)*2;
            __half2 p0 = *(__half2*)&Oc[mb][dt][0];
            __half2 p1 = *(__half2*)&Oc[mb][dt][1];
            sQT[(d+0)*QSTR + r    ] = __float2half(__half2float(p0.x)*inv[mb][0]);
            sQT[(d+1)*QSTR + r    ] = __float2half(__half2float(p0.y)*inv[mb][0]);
            sQT[(d+0)*QSTR + r + 8] = __float2half(__half2float(p1.x)*inv[mb][1]);
            sQT[(d+1)*QSTR + r + 8] = __float2half(__half2float(p1.y)*inv[mb][1]);
        }
    }
    __syncthreads();
    __half* aob = Og + (size_t)bh * HDIM * NPIX + m0;
    #pragma unroll
    for (int i = 0; i < 4; i++) {
        int idx = tid + i*128;
        int d = idx >> 4, seg = idx & 15;
        *(uint4*)(aob + (size_t)d*NPIX + seg*8) = *(const uint4*)&sQT[d*QSTR + seg*8];
    }
}

// ================= launch =================
extern "C" void kernel_launch(void* const* d_in, const int* in_sizes, int n_in,
                              void* d_out, int out_size) {
    const float* high  = (const float*)d_in[0];
    const float* low   = (const float*)d_in[1];
    const float* nhw   = (const float*)d_in[2];
    const float* nhb   = (const float*)d_in[3];
    const float* nlw   = (const float*)d_in[4];
    const float* nlb   = (const float*)d_in[5];
    const float* nfw   = (const float*)d_in[6];
    const float* nfb   = (const float*)d_in[7];
    const float* Wq    = (const float*)d_in[8];
    const float* Wk    = (const float*)d_in[9];
    const float* Wv    = (const float*)d_in[10];
    const float* Wproj = (const float*)d_in[11];
    const float* Wffn1 = (const float*)d_in[12];
    const float* Wffn2 = (const float*)d_in[13];
    const float* ga    = (const float*)d_in[14];
    const float* gf    = (const float*)d_in[15];
    float* out = (float*)d_out;

    float *x;
    __half *q, *k, *v, *ao, *whq, *whk, *whv, *whp, *wh1, *wh2;
    cudaGetSymbolAddress((void**)&q,   g_q);
    cudaGetSymbolAddress((void**)&k,   g_k);
    cudaGetSymbolAddress((void**)&v,   g_v);
    cudaGetSymbolAddress((void**)&ao,  g_ao);
    cudaGetSymbolAddress((void**)&x,   g_x);
    cudaGetSymbolAddress((void**)&whq, g_whq);
    cudaGetSymbolAddress((void**)&whk, g_whk);
    cudaGetSymbolAddress((void**)&whv, g_whv);
    cudaGetSymbolAddress((void**)&whp, g_whp);
    cudaGetSymbolAddress((void**)&wh1, g_wh1);
    cudaGetSymbolAddress((void**)&wh2, g_wh2);

    const float scale = 0.17677669529663687f * 1.44269504088896340736f; // 1/sqrt(32)*log2e
    const int FFN_SMEM = 50176 + 64*SMSTR*2;  // 83968 bytes

    static int inited = 0;
    if (!inited) {
        cudaFuncSetAttribute(fused_ffn, cudaFuncAttributeMaxDynamicSharedMemorySize, FFN_SMEM);
        inited = 1;
    }

    prep_kernel<<<448, 256>>>(high, low, Wq, Wk, Wv, Wproj, Wffn1, Wffn2, scale);

    gemm_qkv<<<dim3(NPIX/64, 2, BATCH), 256>>>(high, low, whq, whk, whv,
                                               nhw, nhb, nlw, nlb, q, k, v);

    flash_mma<<<dim3(NPIX/128, BATCH*HEADS), 128>>>(q, k, v, ao);

    gemm_proj<<<dim3(NPIX/64, 1, BATCH), 256>>>(ao, whp, x, low, ga);

    fused_ffn<<<dim3(NPIX/64, 1, BATCH), 256, FFN_SMEM>>>(x, wh1, wh2, nfw, nfb, out, gf);

    (void)in_sizes; (void)n_in; (void)out_size;
}

// round 16
// speedup vs baseline: 1.0994x; 1.0301x over previous
#include <cuda_runtime.h>
#include <cuda_fp16.h>
#include <math.h>
#include <stdint.h>

#define BATCH 4
#define NPIX  4096
#define CHIGH 256
#define CLOW  128
#define HEADS 4
#define HDIM  32
#define FFN   256

// ======================= helpers =======================
__device__ __forceinline__ uint32_t smem_u32(const void* p) {
    uint32_t a;
    asm("{ .reg .u64 t; cvta.to.shared.u64 t, %1; cvt.u32.u64 %0, t; }" : "=r"(a) : "l"(p));
    return a;
}

#define LDSM_X4(r0, r1, r2, r3, addr) \
    asm volatile("ldmatrix.sync.aligned.m8n8.x4.shared.b16 {%0,%1,%2,%3}, [%4];" \
        : "=r"(r0), "=r"(r1), "=r"(r2), "=r"(r3) : "r"(addr))
#define LDSM_X2(r0, r1, addr) \
    asm volatile("ldmatrix.sync.aligned.m8n8.x2.shared.b16 {%0,%1}, [%2];" \
        : "=r"(r0), "=r"(r1) : "r"(addr))
#define LDSM_X4_T(r0, r1, r2, r3, addr) \
    asm volatile("ldmatrix.sync.aligned.m8n8.x4.trans.shared.b16 {%0,%1,%2,%3}, [%4];" \
        : "=r"(r0), "=r"(r1), "=r"(r2), "=r"(r3) : "r"(addr))
#define LDSM_X2_T(r0, r1, addr) \
    asm volatile("ldmatrix.sync.aligned.m8n8.x2.trans.shared.b16 {%0,%1}, [%2];" \
        : "=r"(r0), "=r"(r1) : "r"(addr))
#define MMA16816(c, a, b) \
    asm volatile("mma.sync.aligned.m16n8k16.row.col.f32.f16.f16.f32 " \
        "{%0,%1,%2,%3}, {%4,%5,%6,%7}, {%8,%9}, {%0,%1,%2,%3};" \
        : "+f"((c)[0]), "+f"((c)[1]), "+f"((c)[2]), "+f"((c)[3]) \
        : "r"((a)[0]), "r"((a)[1]), "r"((a)[2]), "r"((a)[3]), "r"((b)[0]), "r"((b)[1]))
#define MMA16816H(c, a, b) \
    asm volatile("mma.sync.aligned.m16n8k16.row.col.f16.f16.f16.f16 " \
        "{%0,%1}, {%2,%3,%4,%5}, {%6,%7}, {%0,%1};" \
        : "+r"((c)[0]), "+r"((c)[1]) \
        : "r"((a)[0]), "r"((a)[1]), "r"((a)[2]), "r"((a)[3]), "r"((b)[0]), "r"((b)[1]))
#define EX2_F16X2(out, in) \
    asm("ex2.approx.f16x2 %0, %1;" : "=r"(out) : "r"(in))

__device__ __forceinline__ void cpa16(uint32_t dst, const void* src) {
    asm volatile("cp.async.ca.shared.global [%0], [%1], 16;" :: "r"(dst), "l"(src));
}
#define CP_COMMIT() asm volatile("cp.async.commit_group;" ::: "memory")
#define CP_WAIT0()  asm volatile("cp.async.wait_group 0;" ::: "memory")

__device__ __forceinline__ uint32_t pack_hf2(float a, float b) {
    __half2 h = __floats2half2_rn(a, b);
    return *(uint32_t*)&h;
}
__device__ __forceinline__ uint32_t hadd2u(uint32_t a, uint32_t b) {
    __half2 r = __hadd2(*(__half2*)&a, *(__half2*)&b);
    return *(uint32_t*)&r;
}

// ======================= scratch =======================
__device__ __half g_q  [BATCH*CLOW *NPIX];   // [b][c][n], scale*log2e folded
__device__ __half g_k  [BATCH*CLOW *NPIX];
__device__ __half g_v  [BATCH*CLOW *NPIX];
__device__ __half g_ao [BATCH*CLOW *NPIX];
__device__ float  g_x  [BATCH*CLOW *NPIX];
__device__ float g_part[3][BATCH][64][2];
__device__ __half g_whq[CLOW*CHIGH];
__device__ __half g_whk[CLOW*CLOW];
__device__ __half g_whv[CLOW*CLOW];
__device__ __half g_whp[CLOW*CLOW];
__device__ __half g_wh1[FFN*CLOW];
__device__ __half g_wh2[CLOW*FFN];

// ================= fused prep: weight convert + input stats partials =================
__global__ void prep_kernel(const float* __restrict__ high, const float* __restrict__ low,
                            const float* __restrict__ Wq, const float* __restrict__ Wk,
                            const float* __restrict__ Wv, const float* __restrict__ Wp,
                            const float* __restrict__ W1, const float* __restrict__ W2,
                            float qscale) {
    int bx = blockIdx.x;
    if (bx < 192) {
        int which = bx >> 5, sub = bx & 31;
        const float* src; __half* dst; int n; float a = 1.0f;
        switch (which) {
            case 0: src = Wq; dst = g_whq; n = CLOW*CHIGH; a = qscale; break;
            case 1: src = Wk; dst = g_whk; n = CLOW*CLOW;  break;
            case 2: src = Wv; dst = g_whv; n = CLOW*CLOW;  break;
            case 3: src = Wp; dst = g_whp; n = CLOW*CLOW;  break;
            case 4: src = W1; dst = g_wh1; n = FFN*CLOW;   break;
            default: src = W2; dst = g_wh2; n = CLOW*FFN;  break;
        }
        int i = (sub * 256 + threadIdx.x) * 4;
        if (i < n) {
            float4 v = *(const float4*)(src + i);
            uint2 p;
            p.x = pack_hf2(v.x*a, v.y*a);
            p.y = pack_hf2(v.z*a, v.w*a);
            *(uint2*)(dst + i) = p;
        }
    } else {
        int t = bx - 192;
        int z = t >> 7, b = (t >> 5) & 3, ch = t & 31;
        int perSample = z ? CLOW*NPIX : CHIGH*NPIX;
        int perChunk  = perSample / 32;
        const float* p = (z ? low : high) + (size_t)b*perSample + (size_t)ch*perChunk;
        float s = 0.f, ss = 0.f;
        for (int i = threadIdx.x*4; i < perChunk; i += 256*4) {
            float4 v = *(const float4*)(p + i);
            s  += v.x + v.y + v.z + v.w;
            ss += v.x*v.x + v.y*v.y + v.z*v.z + v.w*v.w;
        }
        #pragma unroll
        for (int o = 16; o; o >>= 1) {
            s  += __shfl_xor_sync(0xffffffffu, s,  o);
            ss += __shfl_xor_sync(0xffffffffu, ss, o);
        }
        __shared__ float sh[2][8];
        int w = threadIdx.x >> 5;
        if ((threadIdx.x & 31) == 0) { sh[0][w] = s; sh[1][w] = ss; }
        __syncthreads();
        if (threadIdx.x == 0) {
            float S = 0.f, SS = 0.f;
            #pragma unroll
            for (int i = 0; i < 8; i++) { S += sh[0][i]; SS += sh[1][i]; }
            g_part[z][b][ch][0] = S; g_part[z][b][ch][1] = SS;
        }
    }
}

// ================= fused Q + KV projections (R14-proven) =================
__global__ void __launch_bounds__(256, 2)
gemm_qkv(const float* __restrict__ high, const float* __restrict__ low,
         const __half* __restrict__ whq, const __half* __restrict__ whk,
         const __half* __restrict__ whv,
         const float* __restrict__ nhw, const float* __restrict__ nhb,
         const float* __restrict__ nlw, const float* __restrict__ nlb,
         __half* __restrict__ qo, __half* __restrict__ ko, __half* __restrict__ vo) {
    __shared__ __align__(16) __half sA[2][2][2*64*40];
    __shared__ __align__(16) __half sB[2][32*72];
    __shared__ float s_stat[2];

    const int tid = threadIdx.x, warp = tid >> 5, lane = tid & 31;
    const int g = warp >> 2, wi = warp & 3, wt = tid & 127;
    const int b = blockIdx.z, n0 = blockIdx.x * 64;
    const bool isQ = (blockIdx.y == 0);

    const float* INf = isQ ? high : low;
    const int K = isQ ? CHIGH : CLOW;
    const int sidx = isQ ? 0 : 1;
    const float* nw    = isQ ? nhw : nlw;
    const float* nbias = isQ ? nhb : nlb;
    const int ntiles = isQ ? 1 : 2;
    const __half* Wg = isQ ? whq : (g ? whv : whk);
    const int gbase = (isQ && g) ? 64 : 0;
    __half* outh = isQ ? qo : (g ? vo : ko);

    float mu, rs;
    {
        if (tid < 32) {
            float s = g_part[sidx][b][tid][0], ss = g_part[sidx][b][tid][1];
            #pragma unroll
            for (int o = 16; o; o >>= 1) {
                s  += __shfl_xor_sync(0xffffffffu, s,  o);
                ss += __shfl_xor_sync(0xffffffffu, ss, o);
            }
            if (tid == 0) {
                float cnt = (float)K * (float)NPIX;
                float m = s / cnt;
                float var = ss / cnt - m * m;
                s_stat[0] = m;
                s_stat[1] = rsqrtf(var + 1e-5f);
            }
        }
        __syncthreads();
        mu = s_stat[0]; rs = s_stat[1];
    }

    const int kB = tid >> 3, nsegB = tid & 7;

    auto stageA = [&](int k0, int bf) {
        #pragma unroll
        for (int it = 0; it < 4; it++) {
            if (it < ntiles*2) {
                int idx = wt + it*128;
                int c = idx >> 2, ch = idx & 3;
                cpa16(smem_u32(&sA[bf][g][c*40 + ch*8]),
                      Wg + (size_t)(gbase + c)*K + k0 + ch*8);
            }
        }
    };
    auto loadB = [&](int k0, float4& ra, float4& rb) {
        const float* p = &INf[((size_t)b*K + k0 + kB)*NPIX + n0 + nsegB*8];
        ra = *(const float4*)p;
        rb = *(const float4*)(p + 4);
    };
    auto storeB = [&](int k0, int bf, const float4& ra, const float4& rb) {
        int kk = k0 + kB;
        float s0 = nw[kk]*rs, t0 = nbias[kk] - mu*s0;
        uint4 o;
        o.x = pack_hf2(ra.x*s0+t0, ra.y*s0+t0);
        o.y = pack_hf2(ra.z*s0+t0, ra.w*s0+t0);
        o.z = pack_hf2(rb.x*s0+t0, rb.y*s0+t0);
        o.w = pack_hf2(rb.z*s0+t0, rb.w*s0+t0);
        *(uint4*)&sB[bf][kB*72 + nsegB*8] = o;
    };

    float acc[2][8][4] = {};
    const int nch = K >> 5;

    stageA(0, 0);
    {
        float4 ra, rb;
        loadB(0, ra, rb);
        storeB(0, 0, ra, rb);
    }
    CP_COMMIT();

    for (int i = 0; i < nch; i++) {
        const int bf = i & 1;
        const bool more = (i + 1 < nch);

        float4 ra, rb;
        if (more) loadB((i+1)*32, ra, rb);

        CP_WAIT0();
        __syncthreads();

        if (more) stageA((i+1)*32, bf^1);

        #pragma unroll
        for (int ct = 0; ct < 2; ct++) {
            if (ct < ntiles) {
                uint32_t qa[2][4];
                #pragma unroll
                for (int kc = 0; kc < 2; kc++) {
                    uint32_t addr = smem_u32(&sA[bf][g][(ct*64 + wi*16 + (lane & 15))*40
                                                        + kc*16 + (lane >> 4)*8]);
                    LDSM_X4(qa[kc][0], qa[kc][1], qa[kc][2], qa[kc][3], addr);
                }
                #pragma unroll
                for (int nt = 0; nt < 8; nt++) {
                    uint32_t b0[2], b1[2];
                    uint32_t a0 = smem_u32(&sB[bf][(lane & 15)*72 + nt*8]);
                    LDSM_X2_T(b0[0], b0[1], a0);
                    LDSM_X2_T(b1[0], b1[1], a0 + 16*72*2);
                    MMA16816(acc[ct][nt], qa[0], b0);
                    MMA16816(acc[ct][nt], qa[1], b1);
                }
            }
        }

        if (more) {
            storeB((i+1)*32, bf^1, ra, rb);
            CP_COMMIT();
        }
    }

    #pragma unroll
    for (int ct = 0; ct < 2; ct++) {
        if (ct < ntiles) {
            #pragma unroll
            for (int nt = 0; nt < 8; nt++) {
                int n = nt*8 + (lane & 3)*2;
                int cA = gbase + ct*64 + wi*16 + (lane >> 2), cB = cA + 8;
                size_t oA = ((size_t)b*CLOW + cA)*NPIX + n0 + n;
                size_t oB = ((size_t)b*CLOW + cB)*NPIX + n0 + n;
                *(uint32_t*)&outh[oA] = pack_hf2(acc[ct][nt][0], acc[ct][nt][1]);
                *(uint32_t*)&outh[oB] = pack_hf2(acc[ct][nt][2], acc[ct][nt][3]);
            }
        }
    }
}

// ================= proj GEMM: x = low + ga*Wp@ao, + x-stats partials =================
__global__ void __launch_bounds__(256, 2)
gemm_proj(const __half* __restrict__ INh, const __half* __restrict__ W,
          float* __restrict__ outf, const float* __restrict__ res,
          const float* __restrict__ gamma) {
    __shared__ __align__(16) __half sA[2][2][64*40];
    __shared__ __align__(16) __half sB[2][32*72];

    const int tid = threadIdx.x, warp = tid >> 5, lane = tid & 31;
    const int g = warp >> 2, wi = warp & 3, wt = tid & 127;
    const int b = blockIdx.z, n0 = blockIdx.x * 64;
    const int gbase = g ? 64 : 0;

    const int kB = tid >> 3, nsegB = tid & 7;

    auto stageA = [&](int k0, int bf) {
        #pragma unroll
        for (int it = 0; it < 2; it++) {
            int idx = wt + it*128;
            int c = idx >> 2, ch = idx & 3;
            cpa16(smem_u32(&sA[bf][g][c*40 + ch*8]),
                  W + (size_t)(gbase + c)*CLOW + k0 + ch*8);
        }
    };
    auto stageB = [&](int k0, int bf) {
        cpa16(smem_u32(&sB[bf][kB*72 + nsegB*8]),
              &INh[((size_t)b*CLOW + k0 + kB)*NPIX + n0 + nsegB*8]);
    };

    float acc[8][4] = {};

    stageA(0, 0); stageB(0, 0); CP_COMMIT();
    for (int i = 0; i < 4; i++) {
        const int bf = i & 1;
        CP_WAIT0();
        __syncthreads();
        if (i + 1 < 4) { stageA((i+1)*32, bf^1); stageB((i+1)*32, bf^1); CP_COMMIT(); }

        uint32_t qa[2][4];
        #pragma unroll
        for (int kc = 0; kc < 2; kc++) {
            uint32_t addr = smem_u32(&sA[bf][g][(wi*16 + (lane & 15))*40
                                                + kc*16 + (lane >> 4)*8]);
            LDSM_X4(qa[kc][0], qa[kc][1], qa[kc][2], qa[kc][3], addr);
        }
        #pragma unroll
        for (int nt = 0; nt < 8; nt++) {
            uint32_t b0[2], b1[2];
            uint32_t a0 = smem_u32(&sB[bf][(lane & 15)*72 + nt*8]);
            LDSM_X2_T(b0[0], b0[1], a0);
            LDSM_X2_T(b1[0], b1[1], a0 + 16*72*2);
            MMA16816(acc[nt], qa[0], b0);
            MMA16816(acc[nt], qa[1], b1);
        }
    }

    float gm = gamma[0];
    float s_s = 0.f, s_ss = 0.f;
    #pragma unroll
    for (int nt = 0; nt < 8; nt++) {
        int n = nt*8 + (lane & 3)*2;
        int cA = gbase + wi*16 + (lane >> 2), cB = cA + 8;
        size_t oA = ((size_t)b*CLOW + cA)*NPIX + n0 + n;
        size_t oB = ((size_t)b*CLOW + cB)*NPIX + n0 + n;
        float2 rA = *(const float2*)&res[oA];
        float2 rB = *(const float2*)&res[oB];
        float v0 = rA.x + gm*acc[nt][0], v1 = rA.y + gm*acc[nt][1];
        float v2 = rB.x + gm*acc[nt][2], v3 = rB.y + gm*acc[nt][3];
        *(float2*)&outf[oA] = make_float2(v0, v1);
        *(float2*)&outf[oB] = make_float2(v2, v3);
        s_s  += (v0 + v1) + (v2 + v3);
        s_ss += v0*v0 + v1*v1 + v2*v2 + v3*v3;
    }
    #pragma unroll
    for (int o = 16; o; o >>= 1) {
        s_s  += __shfl_xor_sync(0xffffffffu, s_s,  o);
        s_ss += __shfl_xor_sync(0xffffffffu, s_ss, o);
    }
    __shared__ float shr[2][8];
    if (lane == 0) { shr[0][warp] = s_s; shr[1][warp] = s_ss; }
    __syncthreads();
    if (tid == 0) {
        float S = 0.f, SS = 0.f;
        #pragma unroll
        for (int i = 0; i < 8; i++) { S += shr[0][i]; SS += shr[1][i]; }
        g_part[2][b][blockIdx.x][0] = S; g_part[2][b][blockIdx.x][1] = SS;
    }
}

// ================= fused FFN (R15-proven) =================
#define SMSTR 264
__global__ void __launch_bounds__(256)
fused_ffn(const float* __restrict__ xin,
          const __half* __restrict__ W1, const __half* __restrict__ W2,
          const float* __restrict__ nw, const float* __restrict__ nbias,
          float* __restrict__ outf, const float* __restrict__ gamma) {
    extern __shared__ __align__(16) char smemRaw[];
    __half* sA = (__half*)smemRaw;
    __half* sB = (__half*)(smemRaw + 40960);
    __half* sM = (__half*)(smemRaw + 50176);
    __shared__ float s_stat[2];

    const int tid = threadIdx.x, warp = tid >> 5, lane = tid & 31;
    const int g = warp >> 2, wi = warp & 3, wt = tid & 127;
    const int b = blockIdx.z, n0 = blockIdx.x * 64;

    float mu, rs;
    {
        if (tid < 32) {
            float s = g_part[2][b][tid][0] + g_part[2][b][tid+32][0];
            float ss = g_part[2][b][tid][1] + g_part[2][b][tid+32][1];
            #pragma unroll
            for (int o = 16; o; o >>= 1) {
                s  += __shfl_xor_sync(0xffffffffu, s,  o);
                ss += __shfl_xor_sync(0xffffffffu, ss, o);
            }
            if (tid == 0) {
                float cnt = (float)CLOW * (float)NPIX;
                float m = s / cnt;
                float var = ss / cnt - m * m;
                s_stat[0] = m;
                s_stat[1] = rsqrtf(var + 1e-5f);
            }
        }
        __syncthreads();
        mu = s_stat[0]; rs = s_stat[1];
    }

    const int kB = tid >> 3, nsegB = tid & 7;
    const int gbase = g ? 128 : 0;

    auto stageA = [&](int k0, int bf) {
        #pragma unroll
        for (int it = 0; it < 4; it++) {
            int idx = wt + it*128;
            int c = idx >> 2, ch = idx & 3;
            cpa16(smem_u32(&sA[(bf*2 + g)*5120 + c*40 + ch*8]),
                  W1 + (size_t)(gbase + c)*CLOW + k0 + ch*8);
        }
    };
    auto loadB = [&](int k0, float4& ra, float4& rb) {
        const float* p = &xin[((size_t)b*CLOW + k0 + kB)*NPIX + n0 + nsegB*8];
        ra = *(const float4*)p;
        rb = *(const float4*)(p + 4);
    };
    auto storeB = [&](int k0, int bf, const float4& ra, const float4& rb) {
        int kk = k0 + kB;
        float s0 = nw[kk]*rs, t0 = nbias[kk] - mu*s0;
        uint4 o;
        o.x = pack_hf2(ra.x*s0+t0, ra.y*s0+t0);
        o.y = pack_hf2(ra.z*s0+t0, ra.w*s0+t0);
        o.z = pack_hf2(rb.x*s0+t0, rb.y*s0+t0);
        o.w = pack_hf2(rb.z*s0+t0, rb.w*s0+t0);
        *(uint4*)&sB[bf*2304 + kB*72 + nsegB*8] = o;
    };

    float acc[2][8][4] = {};
    stageA(0, 0);
    {
        float4 ra, rb;
        loadB(0, ra, rb);
        storeB(0, 0, ra, rb);
    }
    CP_COMMIT();

    for (int i = 0; i < 4; i++) {
        const int bf = i & 1;
        const bool more = (i + 1 < 4);
        float4 ra, rb;
        if (more) loadB((i+1)*32, ra, rb);
        CP_WAIT0();
        __syncthreads();
        if (more) stageA((i+1)*32, bf^1);

        #pragma unroll
        for (int ct = 0; ct < 2; ct++) {
            uint32_t qa[2][4];
            #pragma unroll
            for (int kc = 0; kc < 2; kc++) {
                uint32_t addr = smem_u32(&sA[(bf*2 + g)*5120 + (ct*64 + wi*16 + (lane & 15))*40
                                             + kc*16 + (lane >> 4)*8]);
                LDSM_X4(qa[kc][0], qa[kc][1], qa[kc][2], qa[kc][3], addr);
            }
            #pragma unroll
            for (int nt = 0; nt < 8; nt++) {
                uint32_t b0[2], b1[2];
                uint32_t a0 = smem_u32(&sB[bf*2304 + (lane & 15)*72 + nt*8]);
                LDSM_X2_T(b0[0], b0[1], a0);
                LDSM_X2_T(b1[0], b1[1], a0 + 16*72*2);
                MMA16816(acc[ct][nt], qa[0], b0);
                MMA16816(acc[ct][nt], qa[1], b1);
            }
        }

        if (more) {
            storeB((i+1)*32, bf^1, ra, rb);
            CP_COMMIT();
        }
    }

    #pragma unroll
    for (int ct = 0; ct < 2; ct++) {
        #pragma unroll
        for (int nt = 0; nt < 8; nt++) {
            int n = nt*8 + (lane & 3)*2;
            int cA = gbase + ct*64 + wi*16 + (lane >> 2), cB = cA + 8;
            float v0 = acc[ct][nt][0], v1 = acc[ct][nt][1];
            float v2 = acc[ct][nt][2], v3 = acc[ct][nt][3];
            v0 = 0.5f*v0*(1.0f + erff(v0*0.70710678118654752f));
            v1 = 0.5f*v1*(1.0f + erff(v1*0.70710678118654752f));
            v2 = 0.5f*v2*(1.0f + erff(v2*0.70710678118654752f));
            v3 = 0.5f*v3*(1.0f + erff(v3*0.70710678118654752f));
            sM[(n+0)*SMSTR + cA] = __float2half(v0);
            sM[(n+1)*SMSTR + cA] = __float2half(v1);
            sM[(n+0)*SMSTR + cB] = __float2half(v2);
            sM[(n+1)*SMSTR + cB] = __float2half(v3);
        }
    }
    __syncthreads();

    __half* sW = sA;
    auto stageW = [&](int k0, int bf) {
        #pragma unroll
        for (int it = 0; it < 2; it++) {
            int idx = tid + it*256;
            int c = idx >> 2, ch = idx & 3;
            cpa16(smem_u32(&sW[bf*5120 + c*40 + ch*8]),
                  W2 + (size_t)c*FFN + k0 + ch*8);
        }
    };

    float acc2[8][4] = {};
    stageW(0, 0); CP_COMMIT();
    for (int i = 0; i < 8; i++) {
        const int bf = i & 1;
        CP_WAIT0();
        __syncthreads();
        if (i + 1 < 8) { stageW((i+1)*32, bf^1); CP_COMMIT(); }

        uint32_t qa[2][4];
        #pragma unroll
        for (int kc = 0; kc < 2; kc++) {
            uint32_t addr = smem_u32(&sW[bf*5120 + (warp*16 + (lane & 15))*40
                                         + kc*16 + (lane >> 4)*8]);
            LDSM_X4(qa[kc][0], qa[kc][1], qa[kc][2], qa[kc][3], addr);
        }
        #pragma unroll
        for (int nt = 0; nt < 8; nt++) {
            uint32_t b0[2], b1[2];
            uint32_t a0 = smem_u32(&sM[(nt*8 + (lane & 7))*SMSTR + i*32
                                       + ((lane >> 3) & 1)*8]);
            LDSM_X2(b0[0], b0[1], a0);
            LDSM_X2(b1[0], b1[1], a0 + 32);
            MMA16816(acc2[nt], qa[0], b0);
            MMA16816(acc2[nt], qa[1], b1);
        }
    }

    float gm = gamma[0];
    #pragma unroll
    for (int nt = 0; nt < 8; nt++) {
        int n = nt*8 + (lane & 3)*2;
        int cA = warp*16 + (lane >> 2), cB = cA + 8;
        size_t oA = ((size_t)b*CLOW + cA)*NPIX + n0 + n;
        size_t oB = ((size_t)b*CLOW + cB)*NPIX + n0 + n;
        float2 rA = *(const float2*)&xin[oA];
        float2 rB = *(const float2*)&xin[oB];
        *(float2*)&outf[oA] = make_float2(rA.x + gm*acc2[nt][0], rA.y + gm*acc2[nt][1]);
        *(float2*)&outf[oB] = make_float2(rB.x + gm*acc2[nt][2], rB.y + gm*acc2[nt][3]);
    }
}

// ================= flash attention: BM=256 (8 warps), halved K/V L2 traffic =================
#define QSTR 264
#define KVSTR 72

__device__ __forceinline__ void prefetch_kv(__half* sk, __half* sv,
        const __half* Kb, const __half* Vb, int n0, int tid) {
    {
        int row = tid >> 3, col = tid & 7;    // 256 chunks, 1 per thread
        cpa16(smem_u32(&sk[row*KVSTR + col*8]), Kb + (size_t)row*NPIX + n0 + col*8);
        cpa16(smem_u32(&sv[row*KVSTR + col*8]), Vb + (size_t)row*NPIX + n0 + col*8);
    }
}

__global__ void __launch_bounds__(256, 2)
flash_mma(const __half* __restrict__ Qg, const __half* __restrict__ Kg,
          const __half* __restrict__ Vg, __half* __restrict__ Og) {
    __shared__ __align__(16) __half sQT[32*QSTR];   // Q tile [32 d][256 m]; reused for output transpose
    __shared__ __align__(16) __half sK[2][32*KVSTR];
    __shared__ __align__(16) __half sV[2][32*KVSTR];

    const int tid = threadIdx.x, warp = tid >> 5, lane = tid & 31;
    const int bh = blockIdx.y, m0 = blockIdx.x * 256;
    const __half* Qb = Qg + (size_t)bh * HDIM * NPIX + m0;
    const __half* Kb = Kg + (size_t)bh * HDIM * NPIX;
    const __half* Vb = Vg + (size_t)bh * HDIM * NPIX;

    // Q tile: 32 rows x 256 cols = 1024 x 8-half chunks
    #pragma unroll
    for (int i = 0; i < 4; i++) {
        int ch = tid + i * 256;
        int row = ch >> 5, col = ch & 31;
        *(uint4*)&sQT[row*QSTR + col*8] = *(const uint4*)(Qb + (size_t)row*NPIX + col*8);
    }
    prefetch_kv(sK[0], sV[0], Kb, Vb, 0, tid);
    CP_COMMIT();
    __syncthreads();

    // Q A-frags: warp w owns m rows [w*32, w*32+32)
    uint32_t qa[2][2][4];
    #pragma unroll
    for (int mb = 0; mb < 2; mb++)
        #pragma unroll
        for (int kc = 0; kc < 2; kc++) {
            uint32_t addr = smem_u32(&sQT[(kc*16 + ((lane >> 4) & 1)*8 + (lane & 7))*QSTR
                                          + warp*32 + mb*16 + ((lane >> 3) & 1)*8]);
            LDSM_X4_T(qa[mb][kc][0], qa[mb][kc][1], qa[mb][kc][2], qa[mb][kc][3], addr);
        }

    uint32_t Oc[2][4][2] = {};
    float lrow[2][2] = {};

    for (int nb = 0; nb < 64; nb++) {
        const int buf = nb & 1;
        CP_WAIT0();
        __syncthreads();
        if (nb < 63) {
            prefetch_kv(sK[buf^1], sV[buf^1], Kb, Vb, (nb+1)*64, tid);
            CP_COMMIT();
        }

        uint32_t pa[2][4][4];
        #pragma unroll
        for (int nt = 0; nt < 8; nt++) {
            uint32_t bk0[2], bk1[2];
            uint32_t a0 = smem_u32(&sK[buf][(lane & 15)*KVSTR + nt*8]);
            LDSM_X2_T(bk0[0], bk0[1], a0);
            LDSM_X2_T(bk1[0], bk1[1], a0 + 16*KVSTR*2);
            #pragma unroll
            for (int mb = 0; mb < 2; mb++) {
                uint32_t S[2] = {0u, 0u};
                MMA16816H(S, qa[mb][0], bk0);
                MMA16816H(S, qa[mb][1], bk1);
                EX2_F16X2(S[0], S[0]);
                EX2_F16X2(S[1], S[1]);
                pa[mb][nt >> 1][(nt & 1)*2 + 0] = S[0];
                pa[mb][nt >> 1][(nt & 1)*2 + 1] = S[1];
            }
        }

        #pragma unroll
        for (int mb = 0; mb < 2; mb++) {
            uint32_t h0 = hadd2u(pa[mb][0][0], pa[mb][0][2]);
            uint32_t h1 = hadd2u(pa[mb][0][1], pa[mb][0][3]);
            #pragma unroll
            for (int kc = 1; kc < 4; kc++) {
                h0 = hadd2u(h0, hadd2u(pa[mb][kc][0], pa[mb][kc][2]));
                h1 = hadd2u(h1, hadd2u(pa[mb][kc][1], pa[mb][kc][3]));
            }
            float2 f0 = __half22float2(*(__half2*)&h0);
            float2 f1 = __half22float2(*(__half2*)&h1);
            lrow[mb][0] += f0.x + f0.y;
            lrow[mb][1] += f1.x + f1.y;
        }

        #pragma unroll
        for (int kc = 0; kc < 4; kc++)
            #pragma unroll
            for (int dt = 0; dt < 4; dt++) {
                uint32_t vb[2];
                uint32_t addr = smem_u32(&sV[buf][(dt*8 + (lane & 7))*KVSTR
                                                  + kc*16 + ((lane >> 3) & 1)*8]);
                LDSM_X2(vb[0], vb[1], addr);
                MMA16816H(Oc[0][dt], pa[0][kc], vb);
                MMA16816H(Oc[1][dt], pa[1][kc], vb);
            }
    }

    float inv[2][2];
    #pragma unroll
    for (int mb = 0; mb < 2; mb++)
        #pragma unroll
        for (int j = 0; j < 2; j++) {
            float v = lrow[mb][j];
            v += __shfl_xor_sync(0xffffffffu, v, 1);
            v += __shfl_xor_sync(0xffffffffu, v, 2);
            inv[mb][j] = 1.0f / v;
        }

    // epilogue: fp16 transpose aliased over sQT [32 d][256 m]
    __syncthreads();
    #pragma unroll
    for (int mb = 0; mb < 2; mb++) {
        int r = warp*32 + mb*16 + (lane >> 2);
        #pragma unroll
        for (int dt = 0; dt < 4; dt++) {
            int d = dt*8 + (lane & 3)*2;
            __half2 p0 = *(__half2*)&Oc[mb][dt][0];
            __half2 p1 = *(__half2*)&Oc[mb][dt][1];
            sQT[(d+0)*QSTR + r    ] = __float2half(__half2float(p0.x)*inv[mb][0]);
            sQT[(d+1)*QSTR + r    ] = __float2half(__half2float(p0.y)*inv[mb][0]);
            sQT[(d+0)*QSTR + r + 8] = __float2half(__half2float(p1.x)*inv[mb][1]);
            sQT[(d+1)*QSTR + r + 8] = __float2half(__half2float(p1.y)*inv[mb][1]);
        }
    }
    __syncthreads();
    __half* aob = Og + (size_t)bh * HDIM * NPIX + m0;
    #pragma unroll
    for (int i = 0; i < 4; i++) {
        int idx = tid + i*256;
        int d = idx >> 5, seg = idx & 31;
        *(uint4*)(aob + (size_t)d*NPIX + seg*8) = *(const uint4*)&sQT[d*QSTR + seg*8];
    }
}

// ================= launch =================
extern "C" void kernel_launch(void* const* d_in, const int* in_sizes, int n_in,
                              void* d_out, int out_size) {
    const float* high  = (const float*)d_in[0];
    const float* low   = (const float*)d_in[1];
    const float* nhw   = (const float*)d_in[2];
    const float* nhb   = (const float*)d_in[3];
    const float* nlw   = (const float*)d_in[4];
    const float* nlb   = (const float*)d_in[5];
    const float* nfw   = (const float*)d_in[6];
    const float* nfb   = (const float*)d_in[7];
    const float* Wq    = (const float*)d_in[8];
    const float* Wk    = (const float*)d_in[9];
    const float* Wv    = (const float*)d_in[10];
    const float* Wproj = (const float*)d_in[11];
    const float* Wffn1 = (const float*)d_in[12];
    const float* Wffn2 = (const float*)d_in[13];
    const float* ga    = (const float*)d_in[14];
    const float* gf    = (const float*)d_in[15];
    float* out = (float*)d_out;

    float *x;
    __half *q, *k, *v, *ao, *whq, *whk, *whv, *whp, *wh1, *wh2;
    cudaGetSymbolAddress((void**)&q,   g_q);
    cudaGetSymbolAddress((void**)&k,   g_k);
    cudaGetSymbolAddress((void**)&v,   g_v);
    cudaGetSymbolAddress((void**)&ao,  g_ao);
    cudaGetSymbolAddress((void**)&x,   g_x);
    cudaGetSymbolAddress((void**)&whq, g_whq);
    cudaGetSymbolAddress((void**)&whk, g_whk);
    cudaGetSymbolAddress((void**)&whv, g_whv);
    cudaGetSymbolAddress((void**)&whp, g_whp);
    cudaGetSymbolAddress((void**)&wh1, g_wh1);
    cudaGetSymbolAddress((void**)&wh2, g_wh2);

    const float scale = 0.17677669529663687f * 1.44269504088896340736f; // 1/sqrt(32)*log2e
    const int FFN_SMEM = 50176 + 64*SMSTR*2;  // 83968 bytes

    static int inited = 0;
    if (!inited) {
        cudaFuncSetAttribute(fused_ffn, cudaFuncAttributeMaxDynamicSharedMemorySize, FFN_SMEM);
        inited = 1;
    }

    prep_kernel<<<448, 256>>>(high, low, Wq, Wk, Wv, Wproj, Wffn1, Wffn2, scale);

    gemm_qkv<<<dim3(NPIX/64, 2, BATCH), 256>>>(high, low, whq, whk, whv,
                                               nhw, nhb, nlw, nlb, q, k, v);

    flash_mma<<<dim3(NPIX/256, BATCH*HEADS), 256>>>(q, k, v, ao);

    gemm_proj<<<dim3(NPIX/64, 1, BATCH), 256>>>(ao, whp, x, low, ga);

    fused_ffn<<<dim3(NPIX/64, 1, BATCH), 256, FFN_SMEM>>>(x, wh1, wh2, nfw, nfb, out, gf);

    (void)in_sizes; (void)n_in; (void)out_size;
}